// round 2
// baseline (speedup 1.0000x reference)
#include <cuda_runtime.h>

// ---------------- problem dims ----------------
#define Bb   8
#define Hh   64
#define Ww   64
#define Dd   384
#define DIN  768
#define Nn   16
#define Rr   24
#define Kk   4
#define LL   4096          // H*W
#define C56  56            // R + 2N
#define BL   (Bb*LL)       // 32768

// ---------------- scratch (static device globals; no runtime alloc) ----------------
__device__ float g_xm [Bb*LL*DIN];       // xm in (b,l,d); reused as "act" after LN
__device__ float g_z  [Bb*LL*DIN];       // z  in (b,l,d)
__device__ float g_ue [Bb*LL*DIN];       // conv+silu out, row-major spatial,  (b,l,d)
__device__ float g_uo [Bb*LL*DIN];       // conv+silu out, transposed spatial, (b,lT,d)
__device__ float g_G  [(size_t)Bb*Kk*LL*C56];   // x_dbl per source-index j: (b,k,j,c)
__device__ float g_yp [(size_t)Kk*Bb*LL*DIN];   // scan outputs at source index: (k,b,j,d)
__device__ float g_xpwT[Kk*DIN*C56];     // x_proj_weight transposed to (k,d,c)

// ---------------- fast math ----------------
__device__ __forceinline__ float ex2f(float x){ float r; asm("ex2.approx.f32 %0, %1;" : "=f"(r) : "f"(x)); return r; }
__device__ __forceinline__ float lg2f(float x){ float r; asm("lg2.approx.f32 %0, %1;" : "=f"(r) : "f"(x)); return r; }
#define LOG2E 1.4426950408889634f
#define LN2   0.6931471805599453f
__device__ __forceinline__ float fexp(float x){ return ex2f(x*LOG2E); }
__device__ __forceinline__ float fsilu(float x){ return x / (1.f + fexp(-x)); }
__device__ __forceinline__ float fsoftplus(float x){
    // max(x,0) + log1p(exp(-|x|))
    float e = fexp(-fabsf(x));
    return fmaxf(x, 0.f) + LN2 * lg2f(1.f + e);
}

// ---------------- xpw transpose: (k,c,d) -> (k,d,c) ----------------
__global__ void k_xpwT(const float* __restrict__ xpw){
    int i = blockIdx.x*256 + threadIdx.x;
    if (i >= Kk*DIN*C56) return;
    int k = i / (DIN*C56);
    int rem = i - k*DIN*C56;
    int d = rem / C56;
    int c = rem - d*C56;
    g_xpwT[i] = xpw[(k*C56 + c)*DIN + d];
}

// ---------------- GEMM1: x(32768x384) @ W_in(384x1536) -> xm | z ----------------
__global__ void sgemm_xin(const float* __restrict__ A, const float* __restrict__ Bm){
    __shared__ float As[8][128];
    __shared__ float Bs[8][128];
    const int tid = threadIdx.x;
    const int bm = blockIdx.y, bn = blockIdx.x;
    const float* Ab = A + (size_t)bm*128*Dd;
    const float* Bp = Bm + bn*128;

    float acc[8][8];
    #pragma unroll
    for (int i=0;i<8;i++)
        #pragma unroll
        for (int j=0;j<8;j++) acc[i][j]=0.f;

    const int arow = tid>>1, acol = (tid&1)*4;
    const int brow = tid>>5, bcol = (tid&31)*4;
    const int tm = tid>>4, tn = tid&15;

    for (int k0=0;k0<Dd;k0+=8){
        float4 av = *(const float4*)(Ab + (size_t)arow*Dd + k0 + acol);
        As[acol+0][arow]=av.x; As[acol+1][arow]=av.y; As[acol+2][arow]=av.z; As[acol+3][arow]=av.w;
        float4 bv = *(const float4*)(Bp + (size_t)(k0+brow)*(2*DIN) + bcol);
        *(float4*)&Bs[brow][bcol] = bv;
        __syncthreads();
        #pragma unroll
        for (int kk=0;kk<8;kk++){
            float ar[8], br[8];
            *(float4*)&ar[0] = *(const float4*)&As[kk][tm*8];
            *(float4*)&ar[4] = *(const float4*)&As[kk][tm*8+4];
            *(float4*)&br[0] = *(const float4*)&Bs[kk][tn*8];
            *(float4*)&br[4] = *(const float4*)&Bs[kk][tn*8+4];
            #pragma unroll
            for (int i=0;i<8;i++)
                #pragma unroll
                for (int j=0;j<8;j++) acc[i][j] = fmaf(ar[i], br[j], acc[i][j]);
        }
        __syncthreads();
    }
    // N tiles 0..5 -> xm, 6..11 -> z (768 % 128 == 0 so a tile never straddles)
    const bool to_z = (bn >= 6);
    float* dst = to_z ? g_z : g_xm;
    const int cbase = bn*128 - (to_z ? DIN : 0);
    #pragma unroll
    for (int i=0;i<8;i++){
        size_t row = (size_t)bm*128 + tm*8 + i;
        float* p = dst + row*DIN + cbase + tn*8;
        *(float4*)&p[0] = *(float4*)&acc[i][0];
        *(float4*)&p[4] = *(float4*)&acc[i][4];
    }
}

// ---------------- depthwise conv 3x3 + bias + silu; writes ue and uo ----------------
__global__ void k_conv(const float* __restrict__ cw, const float* __restrict__ cb){
    const int d = blockIdx.x*blockDim.x + threadIdx.x;   // 0..767
    const int l = blockIdx.y;                            // 0..4095
    const int b = blockIdx.z;
    const int h = l>>6, w = l&63;
    float wt[9];
    #pragma unroll
    for (int i=0;i<9;i++) wt[i] = cw[d*9+i];
    float acc = cb[d];
    const float* base = g_xm + (size_t)b*LL*DIN + d;
    #pragma unroll
    for (int di=-1; di<=1; di++){
        int hh = h+di;
        if (hh<0 || hh>=Hh) continue;
        #pragma unroll
        for (int dj=-1; dj<=1; dj++){
            int ww2 = w+dj;
            if (ww2<0 || ww2>=Ww) continue;
            acc = fmaf(base[(size_t)(hh*Ww+ww2)*DIN], wt[(di+1)*3 + (dj+1)], acc);
        }
    }
    float v = fsilu(acc);
    g_ue[((size_t)b*LL + l)*DIN + d] = v;
    int lt = w*Hh + h;
    g_uo[((size_t)b*LL + lt)*DIN + d] = v;
}

// ---------------- x_dbl GEMM: G[b,k,j,c] = sum_d u[b,j,d] * xpwT[k,d,c] ----------------
// A: (4096 x 768) row-major (ue or uo plane), B: (768 x 56) row-major. 64x64 tile.
__global__ void sgemm_xdbl(){
    __shared__ float As[8][64];
    __shared__ float Bs[8][64];
    const int tid = threadIdx.x;
    const int z = blockIdx.z;            // b*4 + k
    const int b = z>>2, k = z&3;
    const float* A = ((k&1) ? g_uo : g_ue) + (size_t)b*LL*DIN;
    const float* Bp = g_xpwT + (size_t)k*DIN*C56;
    const int bj = blockIdx.x;

    float acc[4][4];
    #pragma unroll
    for (int i=0;i<4;i++)
        #pragma unroll
        for (int j=0;j<4;j++) acc[i][j]=0.f;

    const int arow = tid>>2, acol = (tid&3)*2;
    const int brw  = tid>>5, bcl  = (tid&31)*2;
    const int tm = tid>>4, tn = tid&15;

    for (int k0=0;k0<DIN;k0+=8){
        float2 av = *(const float2*)(A + ((size_t)bj*64 + arow)*DIN + k0 + acol);
        As[acol][arow] = av.x; As[acol+1][arow] = av.y;
        float b0=0.f, b1=0.f;
        if (bcl < C56){
            const float* bp = Bp + (size_t)(k0+brw)*C56 + bcl;
            b0 = bp[0]; b1 = bp[1];
        }
        Bs[brw][bcl] = b0; Bs[brw][bcl+1] = b1;
        __syncthreads();
        #pragma unroll
        for (int kk=0;kk<8;kk++){
            float ar[4], br[4];
            *(float4*)ar = *(const float4*)&As[kk][tm*4];
            *(float4*)br = *(const float4*)&Bs[kk][tn*4];
            #pragma unroll
            for (int i=0;i<4;i++)
                #pragma unroll
                for (int j=0;j<4;j++) acc[i][j] = fmaf(ar[i], br[j], acc[i][j]);
        }
        __syncthreads();
    }
    #pragma unroll
    for (int i=0;i<4;i++){
        int j = bj*64 + tm*4 + i;
        float* gp = g_G + ((size_t)z*LL + j)*C56 + tn*4;
        #pragma unroll
        for (int jj=0;jj<4;jj++){
            int c = tn*4 + jj;
            if (c < C56) gp[jj] = acc[i][jj];
        }
    }
}

// ---------------- selective scan: one thread per (b,k,d) channel ----------------
__global__ void __launch_bounds__(64) k_scan(const float* __restrict__ dtw_g,
                                             const float* __restrict__ dtb_g,
                                             const float* __restrict__ Alog_g,
                                             const float* __restrict__ Ds_g){
    const int d = blockIdx.x*64 + threadIdx.x;
    const int k = blockIdx.y, b = blockIdx.z;
    const int kd = k*DIN + d;

    float dtw[Rr];
    const float* wp = dtw_g + (size_t)kd*Rr;
    #pragma unroll
    for (int r=0;r<Rr;r++) dtw[r] = wp[r];
    const float bias = dtb_g[kd];
    float al[Nn];
    const float* ap = Alog_g + (size_t)kd*Nn;
    #pragma unroll
    for (int n=0;n<Nn;n++) al[n] = -ex2f(ap[n]*LOG2E) * LOG2E;  // A[n]*log2e (negative)
    const float Dv = Ds_g[kd];

    float h[Nn];
    #pragma unroll
    for (int n=0;n<Nn;n++) h[n]=0.f;

    const float* up = ((k&1) ? g_uo : g_ue) + (size_t)b*LL*DIN + d;
    const float* Gp = g_G + ((size_t)(b*Kk + k))*LL*C56;
    float* yp = g_yp + ((size_t)(k*Bb + b))*LL*DIN + d;
    const bool rev = (k>=2);

    for (int t=0;t<LL;t++){
        const int j = rev ? (LL-1-t) : t;
        const float4* G4 = (const float4*)(Gp + (size_t)j*C56);
        const float u = up[(size_t)j*DIN];

        float gdt[Rr];
        *(float4*)&gdt[0]  = G4[0]; *(float4*)&gdt[4]  = G4[1]; *(float4*)&gdt[8]  = G4[2];
        *(float4*)&gdt[12] = G4[3]; *(float4*)&gdt[16] = G4[4]; *(float4*)&gdt[20] = G4[5];
        float accd = bias;
        #pragma unroll
        for (int r=0;r<Rr;r++) accd = fmaf(dtw[r], gdt[r], accd);
        const float delta = fsoftplus(accd);
        const float du = delta*u;

        float Bv[Nn], Cv[Nn];
        *(float4*)&Bv[0]  = G4[6];  *(float4*)&Bv[4]  = G4[7];
        *(float4*)&Bv[8]  = G4[8];  *(float4*)&Bv[12] = G4[9];
        *(float4*)&Cv[0]  = G4[10]; *(float4*)&Cv[4]  = G4[11];
        *(float4*)&Cv[8]  = G4[12]; *(float4*)&Cv[12] = G4[13];

        float y = 0.f;
        #pragma unroll
        for (int n=0;n<Nn;n++){
            float e = ex2f(delta * al[n]);
            h[n] = fmaf(h[n], e, du*Bv[n]);
            y = fmaf(h[n], Cv[n], y);
        }
        yp[(size_t)j*DIN] = fmaf(Dv, u, y);
    }
}

// ---------------- merge 4 directions + layernorm + gate ----------------
__device__ __forceinline__ float block_sum256(float v, float* sh){
    __syncthreads();
    #pragma unroll
    for (int o=16;o>0;o>>=1) v += __shfl_xor_sync(0xffffffffu, v, o);
    if ((threadIdx.x&31)==0) sh[threadIdx.x>>5] = v;
    __syncthreads();
    if (threadIdx.x < 32){
        float t = (threadIdx.x < 8) ? sh[threadIdx.x] : 0.f;
        #pragma unroll
        for (int o=4;o>0;o>>=1) t += __shfl_xor_sync(0xffffffffu, t, o);
        if (threadIdx.x==0) sh[0]=t;
    }
    __syncthreads();
    return sh[0];
}

__global__ void k_ln(const float* __restrict__ lng, const float* __restrict__ lnb){
    __shared__ float sh[32];
    const int bl = blockIdx.x;            // b*4096 + l
    const int b = bl>>12, l = bl&4095;
    const int lt = (l&63)*Hh + (l>>6);

    float vals[3];
    float s = 0.f;
    #pragma unroll
    for (int i=0;i<3;i++){
        int d = threadIdx.x + i*256;
        size_t i0 = ((size_t)(0*Bb+b)*LL + l )*DIN + d;
        size_t i1 = ((size_t)(1*Bb+b)*LL + lt)*DIN + d;
        size_t i2 = ((size_t)(2*Bb+b)*LL + l )*DIN + d;
        size_t i3 = ((size_t)(3*Bb+b)*LL + lt)*DIN + d;
        float v = g_yp[i0] + g_yp[i2] + g_yp[i1] + g_yp[i3];
        vals[i] = v;
        s += v;
    }
    float tot = block_sum256(s, sh);
    const float mu = tot * (1.f/DIN);
    float s2 = 0.f;
    #pragma unroll
    for (int i=0;i<3;i++){ float c = vals[i]-mu; s2 += c*c; }
    float tot2 = block_sum256(s2, sh);
    const float rstd = rsqrtf(tot2*(1.f/DIN) + 1e-5f);

    #pragma unroll
    for (int i=0;i<3;i++){
        int d = threadIdx.x + i*256;
        float zn = g_z[(size_t)bl*DIN + d];
        float o = (vals[i]-mu)*rstd*lng[d] + lnb[d];
        g_xm[(size_t)bl*DIN + d] = o * fsilu(zn);   // reuse g_xm as act
    }
}

// ---------------- GEMM out: act(32768x768) @ W_out(768x384) -> out ----------------
__global__ void sgemm_out(const float* __restrict__ Bm, float* __restrict__ out){
    __shared__ float As[8][128];
    __shared__ float Bs[8][128];
    const int tid = threadIdx.x;
    const int bm = blockIdx.y, bn = blockIdx.x;
    const float* Ab = g_xm + (size_t)bm*128*DIN;
    const float* Bp = Bm + bn*128;

    float acc[8][8];
    #pragma unroll
    for (int i=0;i<8;i++)
        #pragma unroll
        for (int j=0;j<8;j++) acc[i][j]=0.f;

    const int arow = tid>>1, acol = (tid&1)*4;
    const int brow = tid>>5, bcol = (tid&31)*4;
    const int tm = tid>>4, tn = tid&15;

    for (int k0=0;k0<DIN;k0+=8){
        float4 av = *(const float4*)(Ab + (size_t)arow*DIN + k0 + acol);
        As[acol+0][arow]=av.x; As[acol+1][arow]=av.y; As[acol+2][arow]=av.z; As[acol+3][arow]=av.w;
        float4 bv = *(const float4*)(Bp + (size_t)(k0+brow)*Dd + bcol);
        *(float4*)&Bs[brow][bcol] = bv;
        __syncthreads();
        #pragma unroll
        for (int kk=0;kk<8;kk++){
            float ar[8], br[8];
            *(float4*)&ar[0] = *(const float4*)&As[kk][tm*8];
            *(float4*)&ar[4] = *(const float4*)&As[kk][tm*8+4];
            *(float4*)&br[0] = *(const float4*)&Bs[kk][tn*8];
            *(float4*)&br[4] = *(const float4*)&Bs[kk][tn*8+4];
            #pragma unroll
            for (int i=0;i<8;i++)
                #pragma unroll
                for (int j=0;j<8;j++) acc[i][j] = fmaf(ar[i], br[j], acc[i][j]);
        }
        __syncthreads();
    }
    #pragma unroll
    for (int i=0;i<8;i++){
        size_t row = (size_t)bm*128 + tm*8 + i;
        float* p = out + row*Dd + bn*128 + tn*8;
        *(float4*)&p[0] = *(float4*)&acc[i][0];
        *(float4*)&p[4] = *(float4*)&acc[i][4];
    }
}

// ---------------- launch ----------------
extern "C" void kernel_launch(void* const* d_in, const int* in_sizes, int n_in,
                              void* d_out, int out_size){
    const float* x      = (const float*)d_in[0];
    const float* W_in   = (const float*)d_in[1];
    const float* conv_w = (const float*)d_in[2];
    const float* conv_b = (const float*)d_in[3];
    const float* xpw    = (const float*)d_in[4];
    const float* dtw    = (const float*)d_in[5];
    const float* dtb    = (const float*)d_in[6];
    const float* Alog   = (const float*)d_in[7];
    const float* Ds     = (const float*)d_in[8];
    const float* lng    = (const float*)d_in[9];
    const float* lnb    = (const float*)d_in[10];
    const float* W_out  = (const float*)d_in[11];
    float* out = (float*)d_out;

    k_xpwT<<<(Kk*DIN*C56 + 255)/256, 256>>>(xpw);
    sgemm_xin<<<dim3(12, BL/128), 256>>>(x, W_in);
    k_conv<<<dim3(DIN/256, LL, Bb), 256>>>(conv_w, conv_b);
    sgemm_xdbl<<<dim3(LL/64, 1, Bb*Kk), 256>>>();
    k_scan<<<dim3(DIN/64, Kk, Bb), 64>>>(dtw, dtb, Alog, Ds);
    k_ln<<<BL, 256>>>(lng, lnb);
    sgemm_out<<<dim3(Dd/128, BL/128), 256>>>(W_out, out);
}

// round 3
// speedup vs baseline: 1.3604x; 1.3604x over previous
#include <cuda_runtime.h>

// ---------------- problem dims ----------------
#define Bb   8
#define Hh   64
#define Ww   64
#define Dd   384
#define DIN  768
#define Nn   16
#define Rr   24
#define Kk   4
#define LL   4096          // H*W
#define C56  56            // R + 2N
#define BL   (Bb*LL)       // 32768
#define LC   64            // chunk length for parallel scan
#define NC   (LL/LC)       // 64 chunks

// ---------------- scratch (static device globals; no runtime alloc) ----------------
__device__ float g_xm [Bb*LL*DIN];       // xm in (b,l,d); reused as "act" after LN
__device__ float g_z  [Bb*LL*DIN];       // z  in (b,l,d)
__device__ float g_ue [Bb*LL*DIN];       // conv+silu out, row-major spatial,  (b,l,d)
__device__ float g_uo [Bb*LL*DIN];       // conv+silu out, transposed spatial, (b,lT,d)
__device__ float g_G  [(size_t)Bb*Kk*LL*C56];   // x_dbl per source-index j: (b,k,j,c)
__device__ float g_yp [(size_t)Kk*Bb*LL*DIN];   // scan outputs at source index: (k,b,j,d)
__device__ float g_xpwT[Kk*DIN*C56];     // x_proj_weight transposed to (k,d,c)
__device__ float g_cum[(size_t)Bb*Kk*LL*DIN];     // within-chunk cumulative delta, at source idx j
__device__ float g_hf [(size_t)Bb*Kk*NC*DIN*Nn];  // chunk-final local states
__device__ float g_h0 [(size_t)Bb*Kk*NC*DIN*Nn];  // chunk-entry global states
__device__ float g_al [Kk*DIN*Nn];                // A * log2(e)  (negative)

// ---------------- fast math ----------------
__device__ __forceinline__ float ex2f(float x){ float r; asm("ex2.approx.f32 %0, %1;" : "=f"(r) : "f"(x)); return r; }
__device__ __forceinline__ float lg2f(float x){ float r; asm("lg2.approx.f32 %0, %1;" : "=f"(r) : "f"(x)); return r; }
#define LOG2E 1.4426950408889634f
#define LN2   0.6931471805599453f
__device__ __forceinline__ float fexp(float x){ return ex2f(x*LOG2E); }
__device__ __forceinline__ float fsilu(float x){ return x / (1.f + fexp(-x)); }
__device__ __forceinline__ float fsoftplus(float x){
    float e = fexp(-fabsf(x));
    return fmaxf(x, 0.f) + LN2 * lg2f(1.f + e);
}

// ---------------- prep: xpw transpose + A*log2e table ----------------
__global__ void k_xpwT(const float* __restrict__ xpw){
    int i = blockIdx.x*256 + threadIdx.x;
    if (i >= Kk*DIN*C56) return;
    int k = i / (DIN*C56);
    int rem = i - k*DIN*C56;
    int d = rem / C56;
    int c = rem - d*C56;
    g_xpwT[i] = xpw[(k*C56 + c)*DIN + d];
}
__global__ void k_altab(const float* __restrict__ Alog_g){
    int i = blockIdx.x*256 + threadIdx.x;
    if (i >= Kk*DIN*Nn) return;
    g_al[i] = -fexp(Alog_g[i]) * LOG2E;
}

// ---------------- GEMM1: x(32768x384) @ W_in(384x1536) -> xm | z ----------------
__global__ void sgemm_xin(const float* __restrict__ A, const float* __restrict__ Bm){
    __shared__ float As[8][128];
    __shared__ float Bs[8][128];
    const int tid = threadIdx.x;
    const int bm = blockIdx.y, bn = blockIdx.x;
    const float* Ab = A + (size_t)bm*128*Dd;
    const float* Bp = Bm + bn*128;

    float acc[8][8];
    #pragma unroll
    for (int i=0;i<8;i++)
        #pragma unroll
        for (int j=0;j<8;j++) acc[i][j]=0.f;

    const int arow = tid>>1, acol = (tid&1)*4;
    const int brow = tid>>5, bcol = (tid&31)*4;
    const int tm = tid>>4, tn = tid&15;

    for (int k0=0;k0<Dd;k0+=8){
        float4 av = *(const float4*)(Ab + (size_t)arow*Dd + k0 + acol);
        As[acol+0][arow]=av.x; As[acol+1][arow]=av.y; As[acol+2][arow]=av.z; As[acol+3][arow]=av.w;
        float4 bv = *(const float4*)(Bp + (size_t)(k0+brow)*(2*DIN) + bcol);
        *(float4*)&Bs[brow][bcol] = bv;
        __syncthreads();
        #pragma unroll
        for (int kk=0;kk<8;kk++){
            float ar[8], br[8];
            *(float4*)&ar[0] = *(const float4*)&As[kk][tm*8];
            *(float4*)&ar[4] = *(const float4*)&As[kk][tm*8+4];
            *(float4*)&br[0] = *(const float4*)&Bs[kk][tn*8];
            *(float4*)&br[4] = *(const float4*)&Bs[kk][tn*8+4];
            #pragma unroll
            for (int i=0;i<8;i++)
                #pragma unroll
                for (int j=0;j<8;j++) acc[i][j] = fmaf(ar[i], br[j], acc[i][j]);
        }
        __syncthreads();
    }
    const bool to_z = (bn >= 6);
    float* dst = to_z ? g_z : g_xm;
    const int cbase = bn*128 - (to_z ? DIN : 0);
    #pragma unroll
    for (int i=0;i<8;i++){
        size_t row = (size_t)bm*128 + tm*8 + i;
        float* p = dst + row*DIN + cbase + tn*8;
        *(float4*)&p[0] = *(float4*)&acc[i][0];
        *(float4*)&p[4] = *(float4*)&acc[i][4];
    }
}

// ---------------- depthwise conv 3x3 + bias + silu; writes ue and uo ----------------
__global__ void k_conv(const float* __restrict__ cw, const float* __restrict__ cb){
    const int d = blockIdx.x*blockDim.x + threadIdx.x;
    const int l = blockIdx.y;
    const int b = blockIdx.z;
    const int h = l>>6, w = l&63;
    float wt[9];
    #pragma unroll
    for (int i=0;i<9;i++) wt[i] = cw[d*9+i];
    float acc = cb[d];
    const float* base = g_xm + (size_t)b*LL*DIN + d;
    #pragma unroll
    for (int di=-1; di<=1; di++){
        int hh = h+di;
        if (hh<0 || hh>=Hh) continue;
        #pragma unroll
        for (int dj=-1; dj<=1; dj++){
            int ww2 = w+dj;
            if (ww2<0 || ww2>=Ww) continue;
            acc = fmaf(base[(size_t)(hh*Ww+ww2)*DIN], wt[(di+1)*3 + (dj+1)], acc);
        }
    }
    float v = fsilu(acc);
    g_ue[((size_t)b*LL + l)*DIN + d] = v;
    int lt = w*Hh + h;
    g_uo[((size_t)b*LL + lt)*DIN + d] = v;
}

// ---------------- x_dbl GEMM ----------------
__global__ void sgemm_xdbl(){
    __shared__ float As[8][64];
    __shared__ float Bs[8][64];
    const int tid = threadIdx.x;
    const int z = blockIdx.z;
    const int b = z>>2, k = z&3;
    const float* A = ((k&1) ? g_uo : g_ue) + (size_t)b*LL*DIN;
    const float* Bp = g_xpwT + (size_t)k*DIN*C56;
    const int bj = blockIdx.x;

    float acc[4][4];
    #pragma unroll
    for (int i=0;i<4;i++)
        #pragma unroll
        for (int j=0;j<4;j++) acc[i][j]=0.f;

    const int arow = tid>>2, acol = (tid&3)*2;
    const int brw  = tid>>5, bcl  = (tid&31)*2;
    const int tm = tid>>4, tn = tid&15;

    for (int k0=0;k0<DIN;k0+=8){
        float2 av = *(const float2*)(A + ((size_t)bj*64 + arow)*DIN + k0 + acol);
        As[acol][arow] = av.x; As[acol+1][arow] = av.y;
        float b0=0.f, b1=0.f;
        if (bcl < C56){
            const float* bp = Bp + (size_t)(k0+brw)*C56 + bcl;
            b0 = bp[0]; b1 = bp[1];
        }
        Bs[brw][bcl] = b0; Bs[brw][bcl+1] = b1;
        __syncthreads();
        #pragma unroll
        for (int kk=0;kk<8;kk++){
            float ar[4], br[4];
            *(float4*)ar = *(const float4*)&As[kk][tm*4];
            *(float4*)br = *(const float4*)&Bs[kk][tn*4];
            #pragma unroll
            for (int i=0;i<4;i++)
                #pragma unroll
                for (int j=0;j<4;j++) acc[i][j] = fmaf(ar[i], br[j], acc[i][j]);
        }
        __syncthreads();
    }
    #pragma unroll
    for (int i=0;i<4;i++){
        int j = bj*64 + tm*4 + i;
        float* gp = g_G + ((size_t)z*LL + j)*C56 + tn*4;
        #pragma unroll
        for (int jj=0;jj<4;jj++){
            int c = tn*4 + jj;
            if (c < C56) gp[jj] = acc[i][jj];
        }
    }
}

// ---------------- Pass A: per-chunk local scan (h0=0) ----------------
__global__ void __launch_bounds__(256) k_scanA(const float* __restrict__ dtw_g,
                                               const float* __restrict__ dtb_g,
                                               const float* __restrict__ Ds_g){
    const int d = blockIdx.x*256 + threadIdx.x;
    const int c = blockIdx.y;
    const int z = blockIdx.z;            // b*4 + k
    const int b = z>>2, k = z&3;
    const int kd = k*DIN + d;

    float dtw[Rr];
    const float* wp = dtw_g + (size_t)kd*Rr;
    #pragma unroll
    for (int r=0;r<Rr;r++) dtw[r] = wp[r];
    const float bias = dtb_g[kd];
    float al[Nn];
    const float* ap = g_al + (size_t)kd*Nn;
    #pragma unroll
    for (int n=0;n<Nn;n++) al[n] = ap[n];
    const float Dv = Ds_g[kd];

    float h[Nn];
    #pragma unroll
    for (int n=0;n<Nn;n++) h[n]=0.f;
    float S = 0.f;

    const float* up = ((k&1) ? g_uo : g_ue) + (size_t)b*LL*DIN + d;
    const float* Gp = g_G + (size_t)z*LL*C56;
    float* cump = g_cum + (size_t)z*LL*DIN + d;
    float* yp = g_yp + ((size_t)(k*Bb + b))*LL*DIN + d;
    const bool rev = (k>=2);
    const int t0 = c*LC;

    for (int tt=0; tt<LC; tt++){
        const int t = t0 + tt;
        const int j = rev ? (LL-1-t) : t;
        const float4* G4 = (const float4*)(Gp + (size_t)j*C56);
        const float u = up[(size_t)j*DIN];

        float accd = bias;
        #pragma unroll
        for (int q=0;q<6;q++){
            float4 g4 = G4[q];
            accd = fmaf(dtw[q*4+0], g4.x, accd);
            accd = fmaf(dtw[q*4+1], g4.y, accd);
            accd = fmaf(dtw[q*4+2], g4.z, accd);
            accd = fmaf(dtw[q*4+3], g4.w, accd);
        }
        const float delta = fsoftplus(accd);
        S += delta;
        cump[(size_t)j*DIN] = S;
        const float du = delta*u;

        float y = 0.f;
        #pragma unroll
        for (int g=0; g<4; g++){
            float4 Bv = G4[6+g];
            float4 Cv = G4[10+g];
            float e;
            e = ex2f(delta*al[g*4+0]); h[g*4+0]=fmaf(h[g*4+0],e,du*Bv.x); y=fmaf(h[g*4+0],Cv.x,y);
            e = ex2f(delta*al[g*4+1]); h[g*4+1]=fmaf(h[g*4+1],e,du*Bv.y); y=fmaf(h[g*4+1],Cv.y,y);
            e = ex2f(delta*al[g*4+2]); h[g*4+2]=fmaf(h[g*4+2],e,du*Bv.z); y=fmaf(h[g*4+2],Cv.z,y);
            e = ex2f(delta*al[g*4+3]); h[g*4+3]=fmaf(h[g*4+3],e,du*Bv.w); y=fmaf(h[g*4+3],Cv.w,y);
        }
        yp[(size_t)j*DIN] = fmaf(Dv, u, y);
    }
    float* hf = g_hf + (((size_t)z*NC + c)*DIN + d)*Nn;
    #pragma unroll
    for (int n=0;n<Nn;n++) hf[n] = h[n];
}

// ---------------- Pass B: sequential chunk-state combine ----------------
__global__ void __launch_bounds__(256) k_scanB(){
    const int d = blockIdx.x*256 + threadIdx.x;
    const int z = blockIdx.y;
    const int k = z&3;
    const int kd = k*DIN + d;
    const bool rev = (k>=2);

    float al[Nn];
    const float* ap = g_al + (size_t)kd*Nn;
    #pragma unroll
    for (int n=0;n<Nn;n++) al[n] = ap[n];

    float h0[Nn];
    #pragma unroll
    for (int n=0;n<Nn;n++) h0[n]=0.f;

    for (int c=0;c<NC;c++){
        float* hp = g_h0 + (((size_t)z*NC + c)*DIN + d)*Nn;
        #pragma unroll
        for (int n=0;n<Nn;n++) hp[n] = h0[n];
        const int t_last = c*LC + (LC-1);
        const int j_last = rev ? (LL-1-t_last) : t_last;
        const float S = g_cum[((size_t)z*LL + j_last)*DIN + d];
        const float* hf = g_hf + (((size_t)z*NC + c)*DIN + d)*Nn;
        #pragma unroll
        for (int n=0;n<Nn;n++){
            float e = ex2f(S*al[n]);
            h0[n] = fmaf(h0[n], e, hf[n]);
        }
    }
}

// ---------------- Pass C: apply cross-chunk correction to y ----------------
__global__ void __launch_bounds__(256) k_scanC(){
    const int c = blockIdx.y;
    if (c == 0) return;                   // h0 == 0 for first chunk
    const int d = blockIdx.x*256 + threadIdx.x;
    const int z = blockIdx.z;
    const int b = z>>2, k = z&3;
    const int kd = k*DIN + d;
    const bool rev = (k>=2);

    float al[Nn], h0[Nn];
    const float* ap = g_al + (size_t)kd*Nn;
    const float* hp = g_h0 + (((size_t)z*NC + c)*DIN + d)*Nn;
    #pragma unroll
    for (int n=0;n<Nn;n++){ al[n] = ap[n]; h0[n] = hp[n]; }

    const float* Gp = g_G + (size_t)z*LL*C56 + Rr + Nn;   // C columns
    const float* cump = g_cum + (size_t)z*LL*DIN + d;
    float* yp = g_yp + ((size_t)(k*Bb + b))*LL*DIN + d;
    const int t0 = c*LC;

    for (int tt=0; tt<LC; tt++){
        const int t = t0 + tt;
        const int j = rev ? (LL-1-t) : t;
        const float S = cump[(size_t)j*DIN];
        const float4* C4 = (const float4*)(Gp + (size_t)j*C56);
        float corr = 0.f;
        #pragma unroll
        for (int g=0; g<4; g++){
            float4 Cv = C4[g];
            corr = fmaf(h0[g*4+0]*ex2f(S*al[g*4+0]), Cv.x, corr);
            corr = fmaf(h0[g*4+1]*ex2f(S*al[g*4+1]), Cv.y, corr);
            corr = fmaf(h0[g*4+2]*ex2f(S*al[g*4+2]), Cv.z, corr);
            corr = fmaf(h0[g*4+3]*ex2f(S*al[g*4+3]), Cv.w, corr);
        }
        yp[(size_t)j*DIN] += corr;
    }
}

// ---------------- merge 4 directions + layernorm + gate ----------------
__device__ __forceinline__ float block_sum256(float v, float* sh){
    __syncthreads();
    #pragma unroll
    for (int o=16;o>0;o>>=1) v += __shfl_xor_sync(0xffffffffu, v, o);
    if ((threadIdx.x&31)==0) sh[threadIdx.x>>5] = v;
    __syncthreads();
    if (threadIdx.x < 32){
        float t = (threadIdx.x < 8) ? sh[threadIdx.x] : 0.f;
        #pragma unroll
        for (int o=4;o>0;o>>=1) t += __shfl_xor_sync(0xffffffffu, t, o);
        if (threadIdx.x==0) sh[0]=t;
    }
    __syncthreads();
    return sh[0];
}

__global__ void k_ln(const float* __restrict__ lng, const float* __restrict__ lnb){
    __shared__ float sh[32];
    const int bl = blockIdx.x;
    const int b = bl>>12, l = bl&4095;
    const int lt = (l&63)*Hh + (l>>6);

    float vals[3];
    float s = 0.f;
    #pragma unroll
    for (int i=0;i<3;i++){
        int d = threadIdx.x + i*256;
        size_t i0 = ((size_t)(0*Bb+b)*LL + l )*DIN + d;
        size_t i1 = ((size_t)(1*Bb+b)*LL + lt)*DIN + d;
        size_t i2 = ((size_t)(2*Bb+b)*LL + l )*DIN + d;
        size_t i3 = ((size_t)(3*Bb+b)*LL + lt)*DIN + d;
        float v = g_yp[i0] + g_yp[i2] + g_yp[i1] + g_yp[i3];
        vals[i] = v;
        s += v;
    }
    float tot = block_sum256(s, sh);
    const float mu = tot * (1.f/DIN);
    float s2 = 0.f;
    #pragma unroll
    for (int i=0;i<3;i++){ float cdev = vals[i]-mu; s2 += cdev*cdev; }
    float tot2 = block_sum256(s2, sh);
    const float rstd = rsqrtf(tot2*(1.f/DIN) + 1e-5f);

    #pragma unroll
    for (int i=0;i<3;i++){
        int d = threadIdx.x + i*256;
        float zn = g_z[(size_t)bl*DIN + d];
        float o = (vals[i]-mu)*rstd*lng[d] + lnb[d];
        g_xm[(size_t)bl*DIN + d] = o * fsilu(zn);
    }
}

// ---------------- GEMM out: act(32768x768) @ W_out(768x384) -> out ----------------
__global__ void sgemm_out(const float* __restrict__ Bm, float* __restrict__ out){
    __shared__ float As[8][128];
    __shared__ float Bs[8][128];
    const int tid = threadIdx.x;
    const int bm = blockIdx.y, bn = blockIdx.x;
    const float* Ab = g_xm + (size_t)bm*128*DIN;
    const float* Bp = Bm + bn*128;

    float acc[8][8];
    #pragma unroll
    for (int i=0;i<8;i++)
        #pragma unroll
        for (int j=0;j<8;j++) acc[i][j]=0.f;

    const int arow = tid>>1, acol = (tid&1)*4;
    const int brow = tid>>5, bcol = (tid&31)*4;
    const int tm = tid>>4, tn = tid&15;

    for (int k0=0;k0<DIN;k0+=8){
        float4 av = *(const float4*)(Ab + (size_t)arow*DIN + k0 + acol);
        As[acol+0][arow]=av.x; As[acol+1][arow]=av.y; As[acol+2][arow]=av.z; As[acol+3][arow]=av.w;
        float4 bv = *(const float4*)(Bp + (size_t)(k0+brow)*Dd + bcol);
        *(float4*)&Bs[brow][bcol] = bv;
        __syncthreads();
        #pragma unroll
        for (int kk=0;kk<8;kk++){
            float ar[8], br[8];
            *(float4*)&ar[0] = *(const float4*)&As[kk][tm*8];
            *(float4*)&ar[4] = *(const float4*)&As[kk][tm*8+4];
            *(float4*)&br[0] = *(const float4*)&Bs[kk][tn*8];
            *(float4*)&br[4] = *(const float4*)&Bs[kk][tn*8+4];
            #pragma unroll
            for (int i=0;i<8;i++)
                #pragma unroll
                for (int j=0;j<8;j++) acc[i][j] = fmaf(ar[i], br[j], acc[i][j]);
        }
        __syncthreads();
    }
    #pragma unroll
    for (int i=0;i<8;i++){
        size_t row = (size_t)bm*128 + tm*8 + i;
        float* p = out + row*Dd + bn*128 + tn*8;
        *(float4*)&p[0] = *(float4*)&acc[i][0];
        *(float4*)&p[4] = *(float4*)&acc[i][4];
    }
}

// ---------------- launch ----------------
extern "C" void kernel_launch(void* const* d_in, const int* in_sizes, int n_in,
                              void* d_out, int out_size){
    const float* x      = (const float*)d_in[0];
    const float* W_in   = (const float*)d_in[1];
    const float* conv_w = (const float*)d_in[2];
    const float* conv_b = (const float*)d_in[3];
    const float* xpw    = (const float*)d_in[4];
    const float* dtw    = (const float*)d_in[5];
    const float* dtb    = (const float*)d_in[6];
    const float* Alog   = (const float*)d_in[7];
    const float* Ds     = (const float*)d_in[8];
    const float* lng    = (const float*)d_in[9];
    const float* lnb    = (const float*)d_in[10];
    const float* W_out  = (const float*)d_in[11];
    float* out = (float*)d_out;

    k_xpwT<<<(Kk*DIN*C56 + 255)/256, 256>>>(xpw);
    k_altab<<<(Kk*DIN*Nn + 255)/256, 256>>>(Alog);
    sgemm_xin<<<dim3(12, BL/128), 256>>>(x, W_in);
    k_conv<<<dim3(DIN/256, LL, Bb), 256>>>(conv_w, conv_b);
    sgemm_xdbl<<<dim3(LL/64, 1, Bb*Kk), 256>>>();
    k_scanA<<<dim3(DIN/256, NC, Bb*Kk), 256>>>(dtw, dtb, Ds);
    k_scanB<<<dim3(DIN/256, Bb*Kk), 256>>>();
    k_scanC<<<dim3(DIN/256, NC, Bb*Kk), 256>>>();
    k_ln<<<BL, 256>>>(lng, lnb);
    sgemm_out<<<dim3(Dd/128, BL/128), 256>>>(W_out, out);
}

// round 5
// speedup vs baseline: 1.5893x; 1.1683x over previous
#include <cuda_runtime.h>

// ---------------- problem dims ----------------
#define Bb   8
#define Hh   64
#define Ww   64
#define Dd   384
#define DIN  768
#define Nn   16
#define Rr   24
#define Kk   4
#define LL   4096          // H*W
#define C56  56            // R + 2N
#define BL   (Bb*LL)       // 32768
#define LC   64            // chunk length for parallel scan
#define NC   (LL/LC)       // 64 chunks

// ---------------- scratch ----------------
__device__ float g_xm [Bb*LL*DIN];
__device__ float g_z  [Bb*LL*DIN];
__device__ float g_ue [Bb*LL*DIN];
__device__ float g_uo [Bb*LL*DIN];
__device__ float g_G  [(size_t)Bb*Kk*LL*C56];
__device__ float g_yp [(size_t)Kk*Bb*LL*DIN];
__device__ float g_xpwT[Kk*DIN*C56];
__device__ float g_cum[(size_t)Bb*Kk*LL*DIN];
__device__ float g_hf [(size_t)Bb*Kk*NC*DIN*Nn];
__device__ float g_h0 [(size_t)Bb*Kk*NC*DIN*Nn];
__device__ float g_al [Kk*DIN*Nn];                // A * log2(e)  (negative)

// ---------------- fast math ----------------
__device__ __forceinline__ float ex2f(float x){ float r; asm("ex2.approx.f32 %0, %1;" : "=f"(r) : "f"(x)); return r; }
__device__ __forceinline__ float lg2f(float x){ float r; asm("lg2.approx.f32 %0, %1;" : "=f"(r) : "f"(x)); return r; }
#define LOG2E 1.4426950408889634f
#define LN2   0.6931471805599453f
__device__ __forceinline__ float fexp(float x){ return ex2f(x*LOG2E); }
__device__ __forceinline__ float fsilu(float x){ return x / (1.f + fexp(-x)); }
__device__ __forceinline__ float fsoftplus(float x){
    float e = fexp(-fabsf(x));
    return fmaxf(x, 0.f) + LN2 * lg2f(1.f + e);
}

// geometric powers: e[n] = w^(n+1), n=0..15, log-depth product tree
__device__ __forceinline__ void pow16(float w, float* e){
    e[0]=w;
    e[1]=w*w;
    e[2]=e[1]*w;
    e[3]=e[1]*e[1];
    e[4]=e[3]*e[0];
    e[5]=e[3]*e[1];
    e[6]=e[3]*e[2];
    e[7]=e[3]*e[3];
    e[8]=e[7]*e[0];
    e[9]=e[7]*e[1];
    e[10]=e[7]*e[2];
    e[11]=e[7]*e[3];
    e[12]=e[7]*e[4];
    e[13]=e[7]*e[5];
    e[14]=e[7]*e[6];
    e[15]=e[7]*e[7];
}

// ---------------- prep ----------------
__global__ void k_xpwT(const float* __restrict__ xpw){
    int i = blockIdx.x*256 + threadIdx.x;
    if (i >= Kk*DIN*C56) return;
    int k = i / (DIN*C56);
    int rem = i - k*DIN*C56;
    int d = rem / C56;
    int c = rem - d*C56;
    g_xpwT[i] = xpw[(k*C56 + c)*DIN + d];
}
__global__ void k_altab(const float* __restrict__ Alog_g){
    int i = blockIdx.x*256 + threadIdx.x;
    if (i >= Kk*DIN*Nn) return;
    g_al[i] = -fexp(Alog_g[i]) * LOG2E;
}

// ---------------- GEMM1 (double-buffered): x(32768x384)@W_in(384x1536) -> xm|z ----------------
__global__ void sgemm_xin(const float* __restrict__ A, const float* __restrict__ Bm){
    __shared__ float As[2][8][128];
    __shared__ float Bs[2][8][128];
    const int tid = threadIdx.x;
    const int bm = blockIdx.y, bn = blockIdx.x;
    const float* Ab = A + (size_t)bm*128*Dd;
    const float* Bp = Bm + bn*128;

    float acc[8][8];
    #pragma unroll
    for (int i=0;i<8;i++)
        #pragma unroll
        for (int j=0;j<8;j++) acc[i][j]=0.f;

    const int arow = tid>>1, acol = (tid&1)*4;
    const int brow = tid>>5, bcol = (tid&31)*4;
    const int tm = tid>>4, tn = tid&15;

    float4 av = *(const float4*)(Ab + (size_t)arow*Dd + acol);
    float4 bv = *(const float4*)(Bp + (size_t)brow*(2*DIN) + bcol);
    As[0][acol+0][arow]=av.x; As[0][acol+1][arow]=av.y; As[0][acol+2][arow]=av.z; As[0][acol+3][arow]=av.w;
    *(float4*)&Bs[0][brow][bcol] = bv;
    __syncthreads();

    int buf = 0;
    for (int k0=8; k0<=Dd; k0+=8){
        const bool more = (k0 < Dd);
        if (more){
            av = *(const float4*)(Ab + (size_t)arow*Dd + k0 + acol);
            bv = *(const float4*)(Bp + (size_t)(k0+brow)*(2*DIN) + bcol);
        }
        #pragma unroll
        for (int kk=0;kk<8;kk++){
            float ar[8], br[8];
            *(float4*)&ar[0] = *(const float4*)&As[buf][kk][tm*8];
            *(float4*)&ar[4] = *(const float4*)&As[buf][kk][tm*8+4];
            *(float4*)&br[0] = *(const float4*)&Bs[buf][kk][tn*8];
            *(float4*)&br[4] = *(const float4*)&Bs[buf][kk][tn*8+4];
            #pragma unroll
            for (int i=0;i<8;i++)
                #pragma unroll
                for (int j=0;j<8;j++) acc[i][j] = fmaf(ar[i], br[j], acc[i][j]);
        }
        if (more){
            const int nb = buf^1;
            As[nb][acol+0][arow]=av.x; As[nb][acol+1][arow]=av.y; As[nb][acol+2][arow]=av.z; As[nb][acol+3][arow]=av.w;
            *(float4*)&Bs[nb][brow][bcol] = bv;
            __syncthreads();
            buf = nb;
        }
    }
    const bool to_z = (bn >= 6);
    float* dst = to_z ? g_z : g_xm;
    const int cbase = bn*128 - (to_z ? DIN : 0);
    #pragma unroll
    for (int i=0;i<8;i++){
        size_t row = (size_t)bm*128 + tm*8 + i;
        float* p = dst + row*DIN + cbase + tn*8;
        *(float4*)&p[0] = *(float4*)&acc[i][0];
        *(float4*)&p[4] = *(float4*)&acc[i][4];
    }
}

// ---------------- depthwise conv 3x3 + bias + silu ----------------
__global__ void k_conv(const float* __restrict__ cw, const float* __restrict__ cb){
    const int d = blockIdx.x*blockDim.x + threadIdx.x;
    const int l = blockIdx.y;
    const int b = blockIdx.z;
    const int h = l>>6, w = l&63;
    float wt[9];
    #pragma unroll
    for (int i=0;i<9;i++) wt[i] = cw[d*9+i];
    float acc = cb[d];
    const float* base = g_xm + (size_t)b*LL*DIN + d;
    #pragma unroll
    for (int di=-1; di<=1; di++){
        int hh = h+di;
        if (hh<0 || hh>=Hh) continue;
        #pragma unroll
        for (int dj=-1; dj<=1; dj++){
            int ww2 = w+dj;
            if (ww2<0 || ww2>=Ww) continue;
            acc = fmaf(base[(size_t)(hh*Ww+ww2)*DIN], wt[(di+1)*3 + (dj+1)], acc);
        }
    }
    float v = fsilu(acc);
    g_ue[((size_t)b*LL + l)*DIN + d] = v;
    int lt = w*Hh + h;
    g_uo[((size_t)b*LL + lt)*DIN + d] = v;
}

// ---------------- x_dbl GEMM (double-buffered) ----------------
__global__ void sgemm_xdbl(){
    __shared__ float As[2][8][64];
    __shared__ float Bs[2][8][64];
    const int tid = threadIdx.x;
    const int z = blockIdx.z;
    const int b = z>>2, k = z&3;
    const float* A = ((k&1) ? g_uo : g_ue) + (size_t)b*LL*DIN;
    const float* Bp = g_xpwT + (size_t)k*DIN*C56;
    const int bj = blockIdx.x;

    float acc[4][4];
    #pragma unroll
    for (int i=0;i<4;i++)
        #pragma unroll
        for (int j=0;j<4;j++) acc[i][j]=0.f;

    const int arow = tid>>2, acol = (tid&3)*2;
    const int brw  = tid>>5, bcl  = (tid&31)*2;
    const int tm = tid>>4, tn = tid&15;

    float2 av = *(const float2*)(A + ((size_t)bj*64 + arow)*DIN + acol);
    float b0=0.f, b1=0.f;
    if (bcl < C56){ const float* bp = Bp + (size_t)brw*C56 + bcl; b0=bp[0]; b1=bp[1]; }
    As[0][acol][arow]=av.x; As[0][acol+1][arow]=av.y;
    Bs[0][brw][bcl]=b0; Bs[0][brw][bcl+1]=b1;
    __syncthreads();

    int buf = 0;
    for (int k0=8; k0<=DIN; k0+=8){
        const bool more = (k0 < DIN);
        if (more){
            av = *(const float2*)(A + ((size_t)bj*64 + arow)*DIN + k0 + acol);
            b0=0.f; b1=0.f;
            if (bcl < C56){ const float* bp = Bp + (size_t)(k0+brw)*C56 + bcl; b0=bp[0]; b1=bp[1]; }
        }
        #pragma unroll
        for (int kk=0;kk<8;kk++){
            float ar[4], br[4];
            *(float4*)ar = *(const float4*)&As[buf][kk][tm*4];
            *(float4*)br = *(const float4*)&Bs[buf][kk][tn*4];
            #pragma unroll
            for (int i=0;i<4;i++)
                #pragma unroll
                for (int j=0;j<4;j++) acc[i][j] = fmaf(ar[i], br[j], acc[i][j]);
        }
        if (more){
            const int nb = buf^1;
            As[nb][acol][arow]=av.x; As[nb][acol+1][arow]=av.y;
            Bs[nb][brw][bcl]=b0; Bs[nb][brw][bcl+1]=b1;
            __syncthreads();
            buf = nb;
        }
    }
    #pragma unroll
    for (int i=0;i<4;i++){
        int j = bj*64 + tm*4 + i;
        float* gp = g_G + ((size_t)z*LL + j)*C56 + tn*4;
        #pragma unroll
        for (int jj=0;jj<4;jj++){
            int c = tn*4 + jj;
            if (c < C56) gp[jj] = acc[i][jj];
        }
    }
}

// ---------------- Pass A: per-chunk local scan (h0=0) ----------------
__global__ void __launch_bounds__(256) k_scanA(const float* __restrict__ dtw_g,
                                               const float* __restrict__ dtb_g,
                                               const float* __restrict__ Ds_g){
    const int d = blockIdx.x*256 + threadIdx.x;
    const int c = blockIdx.y;
    const int z = blockIdx.z;            // b*4 + k
    const int b = z>>2, k = z&3;
    const int kd = k*DIN + d;

    float dtw[Rr];
    const float* wp = dtw_g + (size_t)kd*Rr;
    #pragma unroll
    for (int r=0;r<Rr;r++) dtw[r] = wp[r];
    const float bias = dtb_g[kd];
    float al[Nn];
    const float* ap = g_al + (size_t)kd*Nn;
    #pragma unroll
    for (int n=0;n<Nn;n++) al[n] = ap[n];
    const float al0 = al[0];
    bool pw = true;
    #pragma unroll
    for (int n=1;n<Nn;n++) pw = pw && (fabsf(al[n] - (float)(n+1)*al0) <= 1e-5f*fabsf(al[n]));
    const float Dv = Ds_g[kd];

    float h[Nn];
    #pragma unroll
    for (int n=0;n<Nn;n++) h[n]=0.f;
    float S = 0.f;

    const float* up = ((k&1) ? g_uo : g_ue) + (size_t)b*LL*DIN + d;
    const float* Gp = g_G + (size_t)z*LL*C56;
    float* cump = g_cum + (size_t)z*LL*DIN + d;
    float* yp = g_yp + ((size_t)(k*Bb + b))*LL*DIN + d;
    const bool rev = (k>=2);
    const int t0 = c*LC;

    if (pw){
        for (int tt=0; tt<LC; tt++){
            const int t = t0 + tt;
            const int j = rev ? (LL-1-t) : t;
            const float4* G4 = (const float4*)(Gp + (size_t)j*C56);
            const float u = up[(size_t)j*DIN];

            float accd = bias;
            #pragma unroll
            for (int q=0;q<6;q++){
                float4 g4 = G4[q];
                accd = fmaf(dtw[q*4+0], g4.x, accd);
                accd = fmaf(dtw[q*4+1], g4.y, accd);
                accd = fmaf(dtw[q*4+2], g4.z, accd);
                accd = fmaf(dtw[q*4+3], g4.w, accd);
            }
            const float delta = fsoftplus(accd);
            S += delta;
            cump[(size_t)j*DIN] = S;
            const float du = delta*u;

            float e[Nn];
            pow16(ex2f(delta*al0), e);

            float y = 0.f;
            #pragma unroll
            for (int g=0; g<4; g++){
                float4 Bv = G4[6+g];
                float4 Cv = G4[10+g];
                h[g*4+0]=fmaf(h[g*4+0],e[g*4+0],du*Bv.x); y=fmaf(h[g*4+0],Cv.x,y);
                h[g*4+1]=fmaf(h[g*4+1],e[g*4+1],du*Bv.y); y=fmaf(h[g*4+1],Cv.y,y);
                h[g*4+2]=fmaf(h[g*4+2],e[g*4+2],du*Bv.z); y=fmaf(h[g*4+2],Cv.z,y);
                h[g*4+3]=fmaf(h[g*4+3],e[g*4+3],du*Bv.w); y=fmaf(h[g*4+3],Cv.w,y);
            }
            yp[(size_t)j*DIN] = fmaf(Dv, u, y);
        }
    } else {
        for (int tt=0; tt<LC; tt++){
            const int t = t0 + tt;
            const int j = rev ? (LL-1-t) : t;
            const float4* G4 = (const float4*)(Gp + (size_t)j*C56);
            const float u = up[(size_t)j*DIN];

            float accd = bias;
            #pragma unroll
            for (int q=0;q<6;q++){
                float4 g4 = G4[q];
                accd = fmaf(dtw[q*4+0], g4.x, accd);
                accd = fmaf(dtw[q*4+1], g4.y, accd);
                accd = fmaf(dtw[q*4+2], g4.z, accd);
                accd = fmaf(dtw[q*4+3], g4.w, accd);
            }
            const float delta = fsoftplus(accd);
            S += delta;
            cump[(size_t)j*DIN] = S;
            const float du = delta*u;

            float y = 0.f;
            #pragma unroll
            for (int g=0; g<4; g++){
                float4 Bv = G4[6+g];
                float4 Cv = G4[10+g];
                float e;
                e = ex2f(delta*al[g*4+0]); h[g*4+0]=fmaf(h[g*4+0],e,du*Bv.x); y=fmaf(h[g*4+0],Cv.x,y);
                e = ex2f(delta*al[g*4+1]); h[g*4+1]=fmaf(h[g*4+1],e,du*Bv.y); y=fmaf(h[g*4+1],Cv.y,y);
                e = ex2f(delta*al[g*4+2]); h[g*4+2]=fmaf(h[g*4+2],e,du*Bv.z); y=fmaf(h[g*4+2],Cv.z,y);
                e = ex2f(delta*al[g*4+3]); h[g*4+3]=fmaf(h[g*4+3],e,du*Bv.w); y=fmaf(h[g*4+3],Cv.w,y);
            }
            yp[(size_t)j*DIN] = fmaf(Dv, u, y);
        }
    }
    float* hf = g_hf + (((size_t)z*NC + c)*DIN + d)*Nn;
    #pragma unroll
    for (int n=0;n<Nn;n++) hf[n] = h[n];
}

// ---------------- Pass B: sequential chunk-state combine ----------------
__global__ void __launch_bounds__(256) k_scanB(){
    const int d = blockIdx.x*256 + threadIdx.x;
    const int z = blockIdx.y;
    const int k = z&3;
    const int kd = k*DIN + d;
    const bool rev = (k>=2);

    float al[Nn];
    const float* ap = g_al + (size_t)kd*Nn;
    #pragma unroll
    for (int n=0;n<Nn;n++) al[n] = ap[n];

    float h0[Nn];
    #pragma unroll
    for (int n=0;n<Nn;n++) h0[n]=0.f;

    for (int c=0;c<NC;c++){
        float* hp = g_h0 + (((size_t)z*NC + c)*DIN + d)*Nn;
        #pragma unroll
        for (int n=0;n<Nn;n++) hp[n] = h0[n];
        const int t_last = c*LC + (LC-1);
        const int j_last = rev ? (LL-1-t_last) : t_last;
        const float S = g_cum[((size_t)z*LL + j_last)*DIN + d];
        const float* hf = g_hf + (((size_t)z*NC + c)*DIN + d)*Nn;
        #pragma unroll
        for (int n=0;n<Nn;n++){
            float e = ex2f(S*al[n]);
            h0[n] = fmaf(h0[n], e, hf[n]);
        }
    }
}

// ---------------- Pass C: apply cross-chunk correction to y ----------------
__global__ void __launch_bounds__(256) k_scanC(){
    const int c = blockIdx.y;
    if (c == 0) return;
    const int d = blockIdx.x*256 + threadIdx.x;
    const int z = blockIdx.z;
    const int b = z>>2, k = z&3;
    const int kd = k*DIN + d;
    const bool rev = (k>=2);

    float al[Nn], h0[Nn];
    const float* ap = g_al + (size_t)kd*Nn;
    const float* hp = g_h0 + (((size_t)z*NC + c)*DIN + d)*Nn;
    #pragma unroll
    for (int n=0;n<Nn;n++){ al[n] = ap[n]; h0[n] = hp[n]; }
    const float al0 = al[0];
    bool pw = true;
    #pragma unroll
    for (int n=1;n<Nn;n++) pw = pw && (fabsf(al[n] - (float)(n+1)*al0) <= 1e-5f*fabsf(al[n]));

    const float* Gp = g_G + (size_t)z*LL*C56 + Rr + Nn;   // C columns
    const float* cump = g_cum + (size_t)z*LL*DIN + d;
    float* yp = g_yp + ((size_t)(k*Bb + b))*LL*DIN + d;
    const int t0 = c*LC;

    if (pw){
        for (int tt=0; tt<LC; tt++){
            const int t = t0 + tt;
            const int j = rev ? (LL-1-t) : t;
            const float S = cump[(size_t)j*DIN];
            const float4* C4 = (const float4*)(Gp + (size_t)j*C56);
            float e[Nn];
            pow16(ex2f(S*al0), e);
            float corr = 0.f;
            #pragma unroll
            for (int g=0; g<4; g++){
                float4 Cv = C4[g];
                corr = fmaf(h0[g*4+0]*e[g*4+0], Cv.x, corr);
                corr = fmaf(h0[g*4+1]*e[g*4+1], Cv.y, corr);
                corr = fmaf(h0[g*4+2]*e[g*4+2], Cv.z, corr);
                corr = fmaf(h0[g*4+3]*e[g*4+3], Cv.w, corr);
            }
            yp[(size_t)j*DIN] += corr;
        }
    } else {
        for (int tt=0; tt<LC; tt++){
            const int t = t0 + tt;
            const int j = rev ? (LL-1-t) : t;
            const float S = cump[(size_t)j*DIN];
            const float4* C4 = (const float4*)(Gp + (size_t)j*C56);
            float corr = 0.f;
            #pragma unroll
            for (int g=0; g<4; g++){
                float4 Cv = C4[g];
                corr = fmaf(h0[g*4+0]*ex2f(S*al[g*4+0]), Cv.x, corr);
                corr = fmaf(h0[g*4+1]*ex2f(S*al[g*4+1]), Cv.y, corr);
                corr = fmaf(h0[g*4+2]*ex2f(S*al[g*4+2]), Cv.z, corr);
                corr = fmaf(h0[g*4+3]*ex2f(S*al[g*4+3]), Cv.w, corr);
            }
            yp[(size_t)j*DIN] += corr;
        }
    }
}

// ---------------- merge 4 directions + layernorm + gate ----------------
__device__ __forceinline__ float block_sum256(float v, float* sh){
    __syncthreads();
    #pragma unroll
    for (int o=16;o>0;o>>=1) v += __shfl_xor_sync(0xffffffffu, v, o);
    if ((threadIdx.x&31)==0) sh[threadIdx.x>>5] = v;
    __syncthreads();
    if (threadIdx.x < 32){
        float t = (threadIdx.x < 8) ? sh[threadIdx.x] : 0.f;
        #pragma unroll
        for (int o=4;o>0;o>>=1) t += __shfl_xor_sync(0xffffffffu, t, o);
        if (threadIdx.x==0) sh[0]=t;
    }
    __syncthreads();
    return sh[0];
}

__global__ void k_ln(const float* __restrict__ lng, const float* __restrict__ lnb){
    __shared__ float sh[32];
    const int bl = blockIdx.x;
    const int b = bl>>12, l = bl&4095;
    const int lt = (l&63)*Hh + (l>>6);

    float vals[3];
    float s = 0.f;
    #pragma unroll
    for (int i=0;i<3;i++){
        int d = threadIdx.x + i*256;
        size_t i0 = ((size_t)(0*Bb+b)*LL + l )*DIN + d;
        size_t i1 = ((size_t)(1*Bb+b)*LL + lt)*DIN + d;
        size_t i2 = ((size_t)(2*Bb+b)*LL + l )*DIN + d;
        size_t i3 = ((size_t)(3*Bb+b)*LL + lt)*DIN + d;
        float v = g_yp[i0] + g_yp[i2] + g_yp[i1] + g_yp[i3];
        vals[i] = v;
        s += v;
    }
    float tot = block_sum256(s, sh);
    const float mu = tot * (1.f/DIN);
    float s2 = 0.f;
    #pragma unroll
    for (int i=0;i<3;i++){ float cdev = vals[i]-mu; s2 += cdev*cdev; }
    float tot2 = block_sum256(s2, sh);
    const float rstd = rsqrtf(tot2*(1.f/DIN) + 1e-5f);

    #pragma unroll
    for (int i=0;i<3;i++){
        int d = threadIdx.x + i*256;
        float zn = g_z[(size_t)bl*DIN + d];
        float o = (vals[i]-mu)*rstd*lng[d] + lnb[d];
        g_xm[(size_t)bl*DIN + d] = o * fsilu(zn);
    }
}

// ---------------- GEMM out (double-buffered): act(32768x768)@W_out(768x384) ----------------
__global__ void sgemm_out(const float* __restrict__ Bm, float* __restrict__ out){
    __shared__ float As[2][8][128];
    __shared__ float Bs[2][8][128];
    const int tid = threadIdx.x;
    const int bm = blockIdx.y, bn = blockIdx.x;
    const float* Ab = g_xm + (size_t)bm*128*DIN;
    const float* Bp = Bm + bn*128;

    float acc[8][8];
    #pragma unroll
    for (int i=0;i<8;i++)
        #pragma unroll
        for (int j=0;j<8;j++) acc[i][j]=0.f;

    const int arow = tid>>1, acol = (tid&1)*4;
    const int brow = tid>>5, bcol = (tid&31)*4;
    const int tm = tid>>4, tn = tid&15;

    float4 av = *(const float4*)(Ab + (size_t)arow*DIN + acol);
    float4 bv = *(const float4*)(Bp + (size_t)brow*Dd + bcol);
    As[0][acol+0][arow]=av.x; As[0][acol+1][arow]=av.y; As[0][acol+2][arow]=av.z; As[0][acol+3][arow]=av.w;
    *(float4*)&Bs[0][brow][bcol] = bv;
    __syncthreads();

    int buf = 0;
    for (int k0=8; k0<=DIN; k0+=8){
        const bool more = (k0 < DIN);
        if (more){
            av = *(const float4*)(Ab + (size_t)arow*DIN + k0 + acol);
            bv = *(const float4*)(Bp + (size_t)(k0+brow)*Dd + bcol);
        }
        #pragma unroll
        for (int kk=0;kk<8;kk++){
            float ar[8], br[8];
            *(float4*)&ar[0] = *(const float4*)&As[buf][kk][tm*8];
            *(float4*)&ar[4] = *(const float4*)&As[buf][kk][tm*8+4];
            *(float4*)&br[0] = *(const float4*)&Bs[buf][kk][tn*8];
            *(float4*)&br[4] = *(const float4*)&Bs[buf][kk][tn*8+4];
            #pragma unroll
            for (int i=0;i<8;i++)
                #pragma unroll
                for (int j=0;j<8;j++) acc[i][j] = fmaf(ar[i], br[j], acc[i][j]);
        }
        if (more){
            const int nb = buf^1;
            As[nb][acol+0][arow]=av.x; As[nb][acol+1][arow]=av.y; As[nb][acol+2][arow]=av.z; As[nb][acol+3][arow]=av.w;
            *(float4*)&Bs[nb][brow][bcol] = bv;
            __syncthreads();
            buf = nb;
        }
    }
    #pragma unroll
    for (int i=0;i<8;i++){
        size_t row = (size_t)bm*128 + tm*8 + i;
        float* p = out + row*Dd + bn*128 + tn*8;
        *(float4*)&p[0] = *(float4*)&acc[i][0];
        *(float4*)&p[4] = *(float4*)&acc[i][4];
    }
}

// ---------------- launch ----------------
extern "C" void kernel_launch(void* const* d_in, const int* in_sizes, int n_in,
                              void* d_out, int out_size){
    const float* x      = (const float*)d_in[0];
    const float* W_in   = (const float*)d_in[1];
    const float* conv_w = (const float*)d_in[2];
    const float* conv_b = (const float*)d_in[3];
    const float* xpw    = (const float*)d_in[4];
    const float* dtw    = (const float*)d_in[5];
    const float* dtb    = (const float*)d_in[6];
    const float* Alog   = (const float*)d_in[7];
    const float* Ds     = (const float*)d_in[8];
    const float* lng    = (const float*)d_in[9];
    const float* lnb    = (const float*)d_in[10];
    const float* W_out  = (const float*)d_in[11];
    float* out = (float*)d_out;

    k_xpwT<<<(Kk*DIN*C56 + 255)/256, 256>>>(xpw);
    k_altab<<<(Kk*DIN*Nn + 255)/256, 256>>>(Alog);
    sgemm_xin<<<dim3(12, BL/128), 256>>>(x, W_in);
    k_conv<<<dim3(DIN/256, LL, Bb), 256>>>(conv_w, conv_b);
    sgemm_xdbl<<<dim3(LL/64, 1, Bb*Kk), 256>>>();
    k_scanA<<<dim3(DIN/256, NC, Bb*Kk), 256>>>(dtw, dtb, Ds);
    k_scanB<<<dim3(DIN/256, Bb*Kk), 256>>>();
    k_scanC<<<dim3(DIN/256, NC, Bb*Kk), 256>>>();
    k_ln<<<BL, 256>>>(lng, lnb);
    sgemm_out<<<dim3(Dd/128, BL/128), 256>>>(W_out, out);
}

// round 6
// speedup vs baseline: 1.5901x; 1.0005x over previous
#include <cuda_runtime.h>

// ---------------- problem dims ----------------
#define Bb   8
#define Hh   64
#define Ww   64
#define Dd   384
#define DIN  768
#define Nn   16
#define Rr   24
#define Kk   4
#define LL   4096          // H*W
#define C56  56            // R + 2N
#define BL   (Bb*LL)       // 32768
#define LC   64            // chunk length for parallel scan
#define NC   (LL/LC)       // 64 chunks

typedef unsigned long long ull;

// ---------------- scratch ----------------
__device__ float g_xm [Bb*LL*DIN];
__device__ float g_z  [Bb*LL*DIN];
__device__ float g_ue [Bb*LL*DIN];
__device__ float g_uo [Bb*LL*DIN];
__device__ float g_G  [(size_t)Bb*Kk*LL*C56];
__device__ float g_yp [(size_t)Kk*Bb*LL*DIN];
__device__ float g_xpwT[Kk*DIN*C56];
__device__ float g_cum[(size_t)Bb*Kk*LL*DIN];
__device__ float g_hf [(size_t)Bb*Kk*NC*DIN*Nn];
__device__ float g_h0 [(size_t)Bb*Kk*NC*DIN*Nn];
__device__ float g_al [Kk*DIN*Nn];                // A * log2(e)  (negative)

// ---------------- fast math ----------------
__device__ __forceinline__ float ex2f(float x){ float r; asm("ex2.approx.f32 %0, %1;" : "=f"(r) : "f"(x)); return r; }
__device__ __forceinline__ float lg2f(float x){ float r; asm("lg2.approx.f32 %0, %1;" : "=f"(r) : "f"(x)); return r; }
#define LOG2E 1.4426950408889634f
#define LN2   0.6931471805599453f
__device__ __forceinline__ float fexp(float x){ return ex2f(x*LOG2E); }
__device__ __forceinline__ float fsilu(float x){ return x / (1.f + fexp(-x)); }
__device__ __forceinline__ float fsoftplus(float x){
    float e = fexp(-fabsf(x));
    return fmaxf(x, 0.f) + LN2 * lg2f(1.f + e);
}

// ---------------- packed f32x2 FMA (FFMA2 — ptxas never emits this from C++) ----------------
__device__ __forceinline__ ull pk2(float lo, float hi){ ull r; asm("mov.b64 %0, {%1,%2};" : "=l"(r) : "f"(lo), "f"(hi)); return r; }
__device__ __forceinline__ void upk2(ull v, float& lo, float& hi){ asm("mov.b64 {%0,%1}, %2;" : "=f"(lo), "=f"(hi) : "l"(v)); }
__device__ __forceinline__ void ffma2(ull& d, ull a, ull b){ asm("fma.rn.f32x2 %0, %1, %2, %0;" : "+l"(d) : "l"(a), "l"(b)); }

// geometric powers: e[n] = w^(n+1)
__device__ __forceinline__ void pow16(float w, float* e){
    e[0]=w;
    e[1]=w*w;
    e[2]=e[1]*w;
    e[3]=e[1]*e[1];
    e[4]=e[3]*e[0];
    e[5]=e[3]*e[1];
    e[6]=e[3]*e[2];
    e[7]=e[3]*e[3];
    e[8]=e[7]*e[0];
    e[9]=e[7]*e[1];
    e[10]=e[7]*e[2];
    e[11]=e[7]*e[3];
    e[12]=e[7]*e[4];
    e[13]=e[7]*e[5];
    e[14]=e[7]*e[6];
    e[15]=e[7]*e[7];
}

// ---------------- prep ----------------
__global__ void k_xpwT(const float* __restrict__ xpw){
    int i = blockIdx.x*256 + threadIdx.x;
    if (i >= Kk*DIN*C56) return;
    int k = i / (DIN*C56);
    int rem = i - k*DIN*C56;
    int d = rem / C56;
    int c = rem - d*C56;
    g_xpwT[i] = xpw[(k*C56 + c)*DIN + d];
}
__global__ void k_altab(const float* __restrict__ Alog_g){
    int i = blockIdx.x*256 + threadIdx.x;
    if (i >= Kk*DIN*Nn) return;
    g_al[i] = -fexp(Alog_g[i]) * LOG2E;
}

// ---------------- GEMM1 (double-buffered + FFMA2): x(32768x384)@W_in(384x1536) -> xm|z ----------------
__global__ void sgemm_xin(const float* __restrict__ A, const float* __restrict__ Bm){
    __shared__ float As[2][8][128];
    __shared__ float Bs[2][8][128];
    const int tid = threadIdx.x;
    const int bm = blockIdx.y, bn = blockIdx.x;
    const float* Ab = A + (size_t)bm*128*Dd;
    const float* Bp = Bm + bn*128;

    ull acc2[8][4];
    #pragma unroll
    for (int i=0;i<8;i++)
        #pragma unroll
        for (int j=0;j<4;j++) acc2[i][j]=0ull;

    const int arow = tid>>1, acol = (tid&1)*4;
    const int brow = tid>>5, bcol = (tid&31)*4;
    const int tm = tid>>4, tn = tid&15;

    float4 av = *(const float4*)(Ab + (size_t)arow*Dd + acol);
    float4 bv = *(const float4*)(Bp + (size_t)brow*(2*DIN) + bcol);
    As[0][acol+0][arow]=av.x; As[0][acol+1][arow]=av.y; As[0][acol+2][arow]=av.z; As[0][acol+3][arow]=av.w;
    *(float4*)&Bs[0][brow][bcol] = bv;
    __syncthreads();

    int buf = 0;
    for (int k0=8; k0<=Dd; k0+=8){
        const bool more = (k0 < Dd);
        if (more){
            av = *(const float4*)(Ab + (size_t)arow*Dd + k0 + acol);
            bv = *(const float4*)(Bp + (size_t)(k0+brow)*(2*DIN) + bcol);
        }
        #pragma unroll
        for (int kk=0;kk<8;kk++){
            float ar[8];
            *(float4*)&ar[0] = *(const float4*)&As[buf][kk][tm*8];
            *(float4*)&ar[4] = *(const float4*)&As[buf][kk][tm*8+4];
            float4 b0v = *(const float4*)&Bs[buf][kk][tn*8];
            float4 b1v = *(const float4*)&Bs[buf][kk][tn*8+4];
            ull bp2[4];
            bp2[0]=pk2(b0v.x,b0v.y); bp2[1]=pk2(b0v.z,b0v.w);
            bp2[2]=pk2(b1v.x,b1v.y); bp2[3]=pk2(b1v.z,b1v.w);
            #pragma unroll
            for (int i=0;i<8;i++){
                ull as2 = pk2(ar[i], ar[i]);
                #pragma unroll
                for (int jp=0;jp<4;jp++) ffma2(acc2[i][jp], as2, bp2[jp]);
            }
        }
        if (more){
            const int nb = buf^1;
            As[nb][acol+0][arow]=av.x; As[nb][acol+1][arow]=av.y; As[nb][acol+2][arow]=av.z; As[nb][acol+3][arow]=av.w;
            *(float4*)&Bs[nb][brow][bcol] = bv;
            __syncthreads();
            buf = nb;
        }
    }
    const bool to_z = (bn >= 6);
    float* dst = to_z ? g_z : g_xm;
    const int cbase = bn*128 - (to_z ? DIN : 0);
    #pragma unroll
    for (int i=0;i<8;i++){
        float o[8];
        upk2(acc2[i][0], o[0], o[1]);
        upk2(acc2[i][1], o[2], o[3]);
        upk2(acc2[i][2], o[4], o[5]);
        upk2(acc2[i][3], o[6], o[7]);
        size_t row = (size_t)bm*128 + tm*8 + i;
        float* p = dst + row*DIN + cbase + tn*8;
        *(float4*)&p[0] = *(float4*)&o[0];
        *(float4*)&p[4] = *(float4*)&o[4];
    }
}

// ---------------- depthwise conv 3x3 + bias + silu (4 w-positions per thread) ----------------
__global__ void k_conv(const float* __restrict__ cw, const float* __restrict__ cb){
    const int d = blockIdx.x*256 + threadIdx.x;     // 0..767
    const int l0 = blockIdx.y*4;                     // 4 consecutive w, same h row
    const int b = blockIdx.z;
    const int h = l0>>6, w0 = l0&63;

    float wt[9];
    #pragma unroll
    for (int i=0;i<9;i++) wt[i] = cw[d*9+i];
    const float bias = cb[d];
    float acc[4];
    #pragma unroll
    for (int q=0;q<4;q++) acc[q]=bias;

    const float* base = g_xm + (size_t)b*LL*DIN + d;
    #pragma unroll
    for (int di=-1; di<=1; di++){
        int hh = h+di;
        if (hh<0 || hh>=Hh) continue;
        const float* rowp = base + (size_t)hh*Ww*DIN;
        #pragma unroll
        for (int dj=-1; dj<=4; dj++){
            int col = w0+dj;
            if (col<0 || col>=Ww) continue;
            float v = rowp[(size_t)col*DIN];
            #pragma unroll
            for (int q=0;q<4;q++){
                int kx = dj - q + 1;                 // kernel col for output q
                if (kx>=0 && kx<=2) acc[q] = fmaf(v, wt[(di+1)*3 + kx], acc[q]);
            }
        }
    }
    #pragma unroll
    for (int q=0;q<4;q++){
        float v = fsilu(acc[q]);
        int l = l0+q;
        g_ue[((size_t)b*LL + l)*DIN + d] = v;
        int lt = (w0+q)*Hh + h;
        g_uo[((size_t)b*LL + lt)*DIN + d] = v;
    }
}

// ---------------- x_dbl GEMM (double-buffered + FFMA2) ----------------
__global__ void sgemm_xdbl(){
    __shared__ float As[2][8][64];
    __shared__ float Bs[2][8][64];
    const int tid = threadIdx.x;
    const int z = blockIdx.z;
    const int b = z>>2, k = z&3;
    const float* A = ((k&1) ? g_uo : g_ue) + (size_t)b*LL*DIN;
    const float* Bp = g_xpwT + (size_t)k*DIN*C56;
    const int bj = blockIdx.x;

    ull acc2[4][2];
    #pragma unroll
    for (int i=0;i<4;i++){ acc2[i][0]=0ull; acc2[i][1]=0ull; }

    const int arow = tid>>2, acol = (tid&3)*2;
    const int brw  = tid>>5, bcl  = (tid&31)*2;
    const int tm = tid>>4, tn = tid&15;

    float2 av = *(const float2*)(A + ((size_t)bj*64 + arow)*DIN + acol);
    float b0=0.f, b1=0.f;
    if (bcl < C56){ const float* bp = Bp + (size_t)brw*C56 + bcl; b0=bp[0]; b1=bp[1]; }
    As[0][acol][arow]=av.x; As[0][acol+1][arow]=av.y;
    Bs[0][brw][bcl]=b0; Bs[0][brw][bcl+1]=b1;
    __syncthreads();

    int buf = 0;
    for (int k0=8; k0<=DIN; k0+=8){
        const bool more = (k0 < DIN);
        if (more){
            av = *(const float2*)(A + ((size_t)bj*64 + arow)*DIN + k0 + acol);
            b0=0.f; b1=0.f;
            if (bcl < C56){ const float* bp = Bp + (size_t)(k0+brw)*C56 + bcl; b0=bp[0]; b1=bp[1]; }
        }
        #pragma unroll
        for (int kk=0;kk<8;kk++){
            float ar[4];
            *(float4*)ar = *(const float4*)&As[buf][kk][tm*4];
            float4 bv4 = *(const float4*)&Bs[buf][kk][tn*4];
            ull bp0 = pk2(bv4.x,bv4.y), bp1 = pk2(bv4.z,bv4.w);
            #pragma unroll
            for (int i=0;i<4;i++){
                ull as2 = pk2(ar[i], ar[i]);
                ffma2(acc2[i][0], as2, bp0);
                ffma2(acc2[i][1], as2, bp1);
            }
        }
        if (more){
            const int nb = buf^1;
            As[nb][acol][arow]=av.x; As[nb][acol+1][arow]=av.y;
            Bs[nb][brw][bcl]=b0; Bs[nb][brw][bcl+1]=b1;
            __syncthreads();
            buf = nb;
        }
    }
    #pragma unroll
    for (int i=0;i<4;i++){
        float o[4];
        upk2(acc2[i][0], o[0], o[1]);
        upk2(acc2[i][1], o[2], o[3]);
        int j = bj*64 + tm*4 + i;
        float* gp = g_G + ((size_t)z*LL + j)*C56 + tn*4;
        #pragma unroll
        for (int jj=0;jj<4;jj++){
            int c = tn*4 + jj;
            if (c < C56) gp[jj] = o[jj];
        }
    }
}

// ---------------- Pass A: per-chunk local scan (h0=0) ----------------
__global__ void __launch_bounds__(256) k_scanA(const float* __restrict__ dtw_g,
                                               const float* __restrict__ dtb_g,
                                               const float* __restrict__ Ds_g){
    const int d = blockIdx.x*256 + threadIdx.x;
    const int c = blockIdx.y;
    const int z = blockIdx.z;            // b*4 + k
    const int b = z>>2, k = z&3;
    const int kd = k*DIN + d;

    float dtw[Rr];
    const float* wp = dtw_g + (size_t)kd*Rr;
    #pragma unroll
    for (int r=0;r<Rr;r++) dtw[r] = wp[r];
    const float bias = dtb_g[kd];
    float al[Nn];
    const float* ap = g_al + (size_t)kd*Nn;
    #pragma unroll
    for (int n=0;n<Nn;n++) al[n] = ap[n];
    const float al0 = al[0];
    bool pw = true;
    #pragma unroll
    for (int n=1;n<Nn;n++) pw = pw && (fabsf(al[n] - (float)(n+1)*al0) <= 1e-5f*fabsf(al[n]));
    const float Dv = Ds_g[kd];

    float h[Nn];
    #pragma unroll
    for (int n=0;n<Nn;n++) h[n]=0.f;
    float S = 0.f;

    const float* up = ((k&1) ? g_uo : g_ue) + (size_t)b*LL*DIN + d;
    const float* Gp = g_G + (size_t)z*LL*C56;
    float* cump = g_cum + (size_t)z*LL*DIN + d;
    float* yp = g_yp + ((size_t)(k*Bb + b))*LL*DIN + d;
    const bool rev = (k>=2);
    const int t0 = c*LC;

    if (pw){
        for (int tt=0; tt<LC; tt++){
            const int t = t0 + tt;
            const int j = rev ? (LL-1-t) : t;
            const float4* G4 = (const float4*)(Gp + (size_t)j*C56);
            const float u = up[(size_t)j*DIN];

            float accd = bias;
            #pragma unroll
            for (int q=0;q<6;q++){
                float4 g4 = G4[q];
                accd = fmaf(dtw[q*4+0], g4.x, accd);
                accd = fmaf(dtw[q*4+1], g4.y, accd);
                accd = fmaf(dtw[q*4+2], g4.z, accd);
                accd = fmaf(dtw[q*4+3], g4.w, accd);
            }
            const float delta = fsoftplus(accd);
            S += delta;
            cump[(size_t)j*DIN] = S;
            const float du = delta*u;

            float e[Nn];
            pow16(ex2f(delta*al0), e);

            float y = 0.f;
            #pragma unroll
            for (int g=0; g<4; g++){
                float4 Bv = G4[6+g];
                float4 Cv = G4[10+g];
                h[g*4+0]=fmaf(h[g*4+0],e[g*4+0],du*Bv.x); y=fmaf(h[g*4+0],Cv.x,y);
                h[g*4+1]=fmaf(h[g*4+1],e[g*4+1],du*Bv.y); y=fmaf(h[g*4+1],Cv.y,y);
                h[g*4+2]=fmaf(h[g*4+2],e[g*4+2],du*Bv.z); y=fmaf(h[g*4+2],Cv.z,y);
                h[g*4+3]=fmaf(h[g*4+3],e[g*4+3],du*Bv.w); y=fmaf(h[g*4+3],Cv.w,y);
            }
            yp[(size_t)j*DIN] = fmaf(Dv, u, y);
        }
    } else {
        for (int tt=0; tt<LC; tt++){
            const int t = t0 + tt;
            const int j = rev ? (LL-1-t) : t;
            const float4* G4 = (const float4*)(Gp + (size_t)j*C56);
            const float u = up[(size_t)j*DIN];

            float accd = bias;
            #pragma unroll
            for (int q=0;q<6;q++){
                float4 g4 = G4[q];
                accd = fmaf(dtw[q*4+0], g4.x, accd);
                accd = fmaf(dtw[q*4+1], g4.y, accd);
                accd = fmaf(dtw[q*4+2], g4.z, accd);
                accd = fmaf(dtw[q*4+3], g4.w, accd);
            }
            const float delta = fsoftplus(accd);
            S += delta;
            cump[(size_t)j*DIN] = S;
            const float du = delta*u;

            float y = 0.f;
            #pragma unroll
            for (int g=0; g<4; g++){
                float4 Bv = G4[6+g];
                float4 Cv = G4[10+g];
                float e;
                e = ex2f(delta*al[g*4+0]); h[g*4+0]=fmaf(h[g*4+0],e,du*Bv.x); y=fmaf(h[g*4+0],Cv.x,y);
                e = ex2f(delta*al[g*4+1]); h[g*4+1]=fmaf(h[g*4+1],e,du*Bv.y); y=fmaf(h[g*4+1],Cv.y,y);
                e = ex2f(delta*al[g*4+2]); h[g*4+2]=fmaf(h[g*4+2],e,du*Bv.z); y=fmaf(h[g*4+2],Cv.z,y);
                e = ex2f(delta*al[g*4+3]); h[g*4+3]=fmaf(h[g*4+3],e,du*Bv.w); y=fmaf(h[g*4+3],Cv.w,y);
            }
            yp[(size_t)j*DIN] = fmaf(Dv, u, y);
        }
    }
    float* hf = g_hf + (((size_t)z*NC + c)*DIN + d)*Nn;
    #pragma unroll
    for (int n=0;n<Nn;n++) hf[n] = h[n];
}

// ---------------- Pass B: sequential chunk-state combine ----------------
__global__ void __launch_bounds__(256) k_scanB(){
    const int d = blockIdx.x*256 + threadIdx.x;
    const int z = blockIdx.y;
    const int k = z&3;
    const int kd = k*DIN + d;
    const bool rev = (k>=2);

    float al[Nn];
    const float* ap = g_al + (size_t)kd*Nn;
    #pragma unroll
    for (int n=0;n<Nn;n++) al[n] = ap[n];

    float h0[Nn];
    #pragma unroll
    for (int n=0;n<Nn;n++) h0[n]=0.f;

    for (int c=0;c<NC;c++){
        float* hp = g_h0 + (((size_t)z*NC + c)*DIN + d)*Nn;
        #pragma unroll
        for (int n=0;n<Nn;n++) hp[n] = h0[n];
        const int t_last = c*LC + (LC-1);
        const int j_last = rev ? (LL-1-t_last) : t_last;
        const float S = g_cum[((size_t)z*LL + j_last)*DIN + d];
        const float* hf = g_hf + (((size_t)z*NC + c)*DIN + d)*Nn;
        #pragma unroll
        for (int n=0;n<Nn;n++){
            float e = ex2f(S*al[n]);
            h0[n] = fmaf(h0[n], e, hf[n]);
        }
    }
}

// ---------------- Pass C: apply cross-chunk correction to y ----------------
__global__ void __launch_bounds__(256) k_scanC(){
    const int c = blockIdx.y;
    if (c == 0) return;
    const int d = blockIdx.x*256 + threadIdx.x;
    const int z = blockIdx.z;
    const int b = z>>2, k = z&3;
    const int kd = k*DIN + d;
    const bool rev = (k>=2);

    float al[Nn], h0[Nn];
    const float* ap = g_al + (size_t)kd*Nn;
    const float* hp = g_h0 + (((size_t)z*NC + c)*DIN + d)*Nn;
    #pragma unroll
    for (int n=0;n<Nn;n++){ al[n] = ap[n]; h0[n] = hp[n]; }
    const float al0 = al[0];
    bool pw = true;
    #pragma unroll
    for (int n=1;n<Nn;n++) pw = pw && (fabsf(al[n] - (float)(n+1)*al0) <= 1e-5f*fabsf(al[n]));

    const float* Gp = g_G + (size_t)z*LL*C56 + Rr + Nn;   // C columns
    const float* cump = g_cum + (size_t)z*LL*DIN + d;
    float* yp = g_yp + ((size_t)(k*Bb + b))*LL*DIN + d;
    const int t0 = c*LC;

    if (pw){
        for (int tt=0; tt<LC; tt++){
            const int t = t0 + tt;
            const int j = rev ? (LL-1-t) : t;
            const float S = cump[(size_t)j*DIN];
            const float4* C4 = (const float4*)(Gp + (size_t)j*C56);
            float e[Nn];
            pow16(ex2f(S*al0), e);
            float corr = 0.f;
            #pragma unroll
            for (int g=0; g<4; g++){
                float4 Cv = C4[g];
                corr = fmaf(h0[g*4+0]*e[g*4+0], Cv.x, corr);
                corr = fmaf(h0[g*4+1]*e[g*4+1], Cv.y, corr);
                corr = fmaf(h0[g*4+2]*e[g*4+2], Cv.z, corr);
                corr = fmaf(h0[g*4+3]*e[g*4+3], Cv.w, corr);
            }
            yp[(size_t)j*DIN] += corr;
        }
    } else {
        for (int tt=0; tt<LC; tt++){
            const int t = t0 + tt;
            const int j = rev ? (LL-1-t) : t;
            const float S = cump[(size_t)j*DIN];
            const float4* C4 = (const float4*)(Gp + (size_t)j*C56);
            float corr = 0.f;
            #pragma unroll
            for (int g=0; g<4; g++){
                float4 Cv = C4[g];
                corr = fmaf(h0[g*4+0]*ex2f(S*al[g*4+0]), Cv.x, corr);
                corr = fmaf(h0[g*4+1]*ex2f(S*al[g*4+1]), Cv.y, corr);
                corr = fmaf(h0[g*4+2]*ex2f(S*al[g*4+2]), Cv.z, corr);
                corr = fmaf(h0[g*4+3]*ex2f(S*al[g*4+3]), Cv.w, corr);
            }
            yp[(size_t)j*DIN] += corr;
        }
    }
}

// ---------------- merge 4 directions + layernorm + gate ----------------
__device__ __forceinline__ float block_sum256(float v, float* sh){
    __syncthreads();
    #pragma unroll
    for (int o=16;o>0;o>>=1) v += __shfl_xor_sync(0xffffffffu, v, o);
    if ((threadIdx.x&31)==0) sh[threadIdx.x>>5] = v;
    __syncthreads();
    if (threadIdx.x < 32){
        float t = (threadIdx.x < 8) ? sh[threadIdx.x] : 0.f;
        #pragma unroll
        for (int o=4;o>0;o>>=1) t += __shfl_xor_sync(0xffffffffu, t, o);
        if (threadIdx.x==0) sh[0]=t;
    }
    __syncthreads();
    return sh[0];
}

__global__ void k_ln(const float* __restrict__ lng, const float* __restrict__ lnb){
    __shared__ float sh[32];
    const int bl = blockIdx.x;
    const int b = bl>>12, l = bl&4095;
    const int lt = (l&63)*Hh + (l>>6);

    float vals[3];
    float s = 0.f;
    #pragma unroll
    for (int i=0;i<3;i++){
        int d = threadIdx.x + i*256;
        size_t i0 = ((size_t)(0*Bb+b)*LL + l )*DIN + d;
        size_t i1 = ((size_t)(1*Bb+b)*LL + lt)*DIN + d;
        size_t i2 = ((size_t)(2*Bb+b)*LL + l )*DIN + d;
        size_t i3 = ((size_t)(3*Bb+b)*LL + lt)*DIN + d;
        float v = g_yp[i0] + g_yp[i2] + g_yp[i1] + g_yp[i3];
        vals[i] = v;
        s += v;
    }
    float tot = block_sum256(s, sh);
    const float mu = tot * (1.f/DIN);
    float s2 = 0.f;
    #pragma unroll
    for (int i=0;i<3;i++){ float cdev = vals[i]-mu; s2 += cdev*cdev; }
    float tot2 = block_sum256(s2, sh);
    const float rstd = rsqrtf(tot2*(1.f/DIN) + 1e-5f);

    #pragma unroll
    for (int i=0;i<3;i++){
        int d = threadIdx.x + i*256;
        float zn = g_z[(size_t)bl*DIN + d];
        float o = (vals[i]-mu)*rstd*lng[d] + lnb[d];
        g_xm[(size_t)bl*DIN + d] = o * fsilu(zn);
    }
}

// ---------------- GEMM out (double-buffered + FFMA2): act(32768x768)@W_out(768x384) ----------------
__global__ void sgemm_out(const float* __restrict__ Bm, float* __restrict__ out){
    __shared__ float As[2][8][128];
    __shared__ float Bs[2][8][128];
    const int tid = threadIdx.x;
    const int bm = blockIdx.y, bn = blockIdx.x;
    const float* Ab = g_xm + (size_t)bm*128*DIN;
    const float* Bp = Bm + bn*128;

    ull acc2[8][4];
    #pragma unroll
    for (int i=0;i<8;i++)
        #pragma unroll
        for (int j=0;j<4;j++) acc2[i][j]=0ull;

    const int arow = tid>>1, acol = (tid&1)*4;
    const int brow = tid>>5, bcol = (tid&31)*4;
    const int tm = tid>>4, tn = tid&15;

    float4 av = *(const float4*)(Ab + (size_t)arow*DIN + acol);
    float4 bv = *(const float4*)(Bp + (size_t)brow*Dd + bcol);
    As[0][acol+0][arow]=av.x; As[0][acol+1][arow]=av.y; As[0][acol+2][arow]=av.z; As[0][acol+3][arow]=av.w;
    *(float4*)&Bs[0][brow][bcol] = bv;
    __syncthreads();

    int buf = 0;
    for (int k0=8; k0<=DIN; k0+=8){
        const bool more = (k0 < DIN);
        if (more){
            av = *(const float4*)(Ab + (size_t)arow*DIN + k0 + acol);
            bv = *(const float4*)(Bp + (size_t)(k0+brow)*Dd + bcol);
        }
        #pragma unroll
        for (int kk=0;kk<8;kk++){
            float ar[8];
            *(float4*)&ar[0] = *(const float4*)&As[buf][kk][tm*8];
            *(float4*)&ar[4] = *(const float4*)&As[buf][kk][tm*8+4];
            float4 b0v = *(const float4*)&Bs[buf][kk][tn*8];
            float4 b1v = *(const float4*)&Bs[buf][kk][tn*8+4];
            ull bp2[4];
            bp2[0]=pk2(b0v.x,b0v.y); bp2[1]=pk2(b0v.z,b0v.w);
            bp2[2]=pk2(b1v.x,b1v.y); bp2[3]=pk2(b1v.z,b1v.w);
            #pragma unroll
            for (int i=0;i<8;i++){
                ull as2 = pk2(ar[i], ar[i]);
                #pragma unroll
                for (int jp=0;jp<4;jp++) ffma2(acc2[i][jp], as2, bp2[jp]);
            }
        }
        if (more){
            const int nb = buf^1;
            As[nb][acol+0][arow]=av.x; As[nb][acol+1][arow]=av.y; As[nb][acol+2][arow]=av.z; As[nb][acol+3][arow]=av.w;
            *(float4*)&Bs[nb][brow][bcol] = bv;
            __syncthreads();
            buf = nb;
        }
    }
    #pragma unroll
    for (int i=0;i<8;i++){
        float o[8];
        upk2(acc2[i][0], o[0], o[1]);
        upk2(acc2[i][1], o[2], o[3]);
        upk2(acc2[i][2], o[4], o[5]);
        upk2(acc2[i][3], o[6], o[7]);
        size_t row = (size_t)bm*128 + tm*8 + i;
        float* p = out + row*Dd + bn*128 + tn*8;
        *(float4*)&p[0] = *(float4*)&o[0];
        *(float4*)&p[4] = *(float4*)&o[4];
    }
}

// ---------------- launch ----------------
extern "C" void kernel_launch(void* const* d_in, const int* in_sizes, int n_in,
                              void* d_out, int out_size){
    const float* x      = (const float*)d_in[0];
    const float* W_in   = (const float*)d_in[1];
    const float* conv_w = (const float*)d_in[2];
    const float* conv_b = (const float*)d_in[3];
    const float* xpw    = (const float*)d_in[4];
    const float* dtw    = (const float*)d_in[5];
    const float* dtb    = (const float*)d_in[6];
    const float* Alog   = (const float*)d_in[7];
    const float* Ds     = (const float*)d_in[8];
    const float* lng    = (const float*)d_in[9];
    const float* lnb    = (const float*)d_in[10];
    const float* W_out  = (const float*)d_in[11];
    float* out = (float*)d_out;

    k_xpwT<<<(Kk*DIN*C56 + 255)/256, 256>>>(xpw);
    k_altab<<<(Kk*DIN*Nn + 255)/256, 256>>>(Alog);
    sgemm_xin<<<dim3(12, BL/128), 256>>>(x, W_in);
    k_conv<<<dim3(DIN/256, LL/4, Bb), 256>>>(conv_w, conv_b);
    sgemm_xdbl<<<dim3(LL/64, 1, Bb*Kk), 256>>>();
    k_scanA<<<dim3(DIN/256, NC, Bb*Kk), 256>>>(dtw, dtb, Ds);
    k_scanB<<<dim3(DIN/256, Bb*Kk), 256>>>();
    k_scanC<<<dim3(DIN/256, NC, Bb*Kk), 256>>>();
    k_ln<<<BL, 256>>>(lng, lnb);
    sgemm_out<<<dim3(Dd/128, BL/128), 256>>>(W_out, out);
}

// round 12
// speedup vs baseline: 1.9081x; 1.2000x over previous
#include <cuda_runtime.h>
#include <cuda_bf16.h>

// ---------------- problem dims ----------------
#define Bb   8
#define Hh   64
#define Ww   64
#define Dd   384
#define DIN  768
#define Nn   16
#define Rr   24
#define Kk   4
#define LL   4096          // H*W
#define C56  56            // R + 2N
#define BL   (Bb*LL)       // 32768
#define LC   64            // chunk length for parallel scan
#define NC   (LL/LC)       // 64 chunks

typedef unsigned int       u32;
typedef unsigned long long u64;

// ---------------- scratch ----------------
__device__ float g_xm [Bb*LL*DIN];
__device__ float g_z  [Bb*LL*DIN];
__device__ float g_ue [Bb*LL*DIN];
__device__ float g_uo [Bb*LL*DIN];
__device__ float g_G  [(size_t)Bb*Kk*LL*C56];
__device__ float g_yp [(size_t)Kk*Bb*LL*DIN];
__device__ float g_xpwT[Kk*DIN*C56];
__device__ float g_cum[(size_t)Bb*Kk*LL*DIN];
__device__ float g_hf [(size_t)Bb*Kk*NC*DIN*Nn];
__device__ float g_h0 [(size_t)Bb*Kk*NC*DIN*Nn];
__device__ float g_al [Kk*DIN*Nn];                // A * log2(e)  (negative)
__device__ __nv_bfloat16 g_xhi[(size_t)BL*Dd];    // x split hi
__device__ __nv_bfloat16 g_xlo[(size_t)BL*Dd];    // x split lo
__device__ __nv_bfloat16 g_ahi[(size_t)BL*DIN];   // act split hi
__device__ __nv_bfloat16 g_alo[(size_t)BL*DIN];   // act split lo

// ---------------- fast math ----------------
__device__ __forceinline__ float ex2f(float x){ float r; asm("ex2.approx.f32 %0, %1;" : "=f"(r) : "f"(x)); return r; }
__device__ __forceinline__ float lg2f(float x){ float r; asm("lg2.approx.f32 %0, %1;" : "=f"(r) : "f"(x)); return r; }
#define LOG2E 1.4426950408889634f
#define LN2   0.6931471805599453f
__device__ __forceinline__ float fexp(float x){ return ex2f(x*LOG2E); }
__device__ __forceinline__ float fsilu(float x){ return x / (1.f + fexp(-x)); }
__device__ __forceinline__ float fsoftplus(float x){
    float e = fexp(-fabsf(x));
    return fmaxf(x, 0.f) + LN2 * lg2f(1.f + e);
}

// geometric powers: e[n] = w^(n+1)
__device__ __forceinline__ void pow16(float w, float* e){
    e[0]=w;  e[1]=w*w; e[2]=e[1]*w; e[3]=e[1]*e[1];
    e[4]=e[3]*e[0]; e[5]=e[3]*e[1]; e[6]=e[3]*e[2]; e[7]=e[3]*e[3];
    e[8]=e[7]*e[0]; e[9]=e[7]*e[1]; e[10]=e[7]*e[2]; e[11]=e[7]*e[3];
    e[12]=e[7]*e[4]; e[13]=e[7]*e[5]; e[14]=e[7]*e[6]; e[15]=e[7]*e[7];
}

// ---------------- warp-mma helpers (sm_80+ features, valid on plain sm_103) ----------------
__device__ __forceinline__ u32 s2u(const void* p){
    u32 a; asm("{ .reg .u64 t; cvta.to.shared.u64 t, %1; cvt.u32.u64 %0, t; }" : "=r"(a) : "l"(p)); return a;
}
__device__ __forceinline__ void ldsm4(u32* r, u32 addr){
    asm volatile("ldmatrix.sync.aligned.m8n8.x4.shared.b16 {%0,%1,%2,%3}, [%4];"
                 : "=r"(r[0]), "=r"(r[1]), "=r"(r[2]), "=r"(r[3]) : "r"(addr));
}
__device__ __forceinline__ void mma16816(float* c, const u32* a, const u32* b){
    asm volatile("mma.sync.aligned.m16n8k16.row.col.f32.bf16.bf16.f32 "
                 "{%0,%1,%2,%3}, {%4,%5,%6,%7}, {%8,%9}, {%0,%1,%2,%3};"
                 : "+f"(c[0]), "+f"(c[1]), "+f"(c[2]), "+f"(c[3])
                 : "r"(a[0]), "r"(a[1]), "r"(a[2]), "r"(a[3]), "r"(b[0]), "r"(b[1]));
}

// ---------------- prep ----------------
__global__ void k_xpwT(const float* __restrict__ xpw){
    int i = blockIdx.x*256 + threadIdx.x;
    if (i >= Kk*DIN*C56) return;
    int k = i / (DIN*C56);
    int rem = i - k*DIN*C56;
    int d = rem / C56;
    int c = rem - d*C56;
    g_xpwT[i] = xpw[(k*C56 + c)*DIN + d];
}
__global__ void k_altab(const float* __restrict__ Alog_g){
    int i = blockIdx.x*256 + threadIdx.x;
    if (i >= Kk*DIN*Nn) return;
    g_al[i] = -fexp(Alog_g[i]) * LOG2E;
}
__global__ void k_cvt_x(const float* __restrict__ in){
    int i = blockIdx.x*256 + threadIdx.x;
    if (i >= BL*Dd) return;
    float v = in[i];
    __nv_bfloat16 h = __float2bfloat16(v);
    g_xhi[i] = h;
    g_xlo[i] = __float2bfloat16(v - __bfloat162float(h));
}

// ---------------- bf16 3-product warp-MMA GEMM ----------------
// MODE 0: xin — A = g_xhi/g_xlo (BL x 384),  B = W_in (384x1536), out -> g_xm | g_z
// MODE 1: out — A = g_ahi/g_alo (BL x 768),  B = W_out (768x384), out -> outp
// Block: 128(M) x 128(N), 8 warps in 2x4, warp tile 64x32, K staged 32.
#define ASTRIDE 20   // u32 per A smem row (40 bf16, padded)
#define BSTRIDE 40   // bf16 per B smem row (padded)
template<int MODE>
__global__ void __launch_bounds__(256, 2) hgemm(const float* __restrict__ Bw, float* __restrict__ outp){
    constexpr int K    = (MODE==0) ? Dd : DIN;
    constexpr int NTOT = (MODE==0) ? 2*DIN : Dd;
    const __nv_bfloat16* Ahi = (MODE==0) ? g_xhi : g_ahi;
    const __nv_bfloat16* Alo = (MODE==0) ? g_xlo : g_alo;

    __shared__ u32 Ash[128*ASTRIDE];
    __shared__ u32 Asl[128*ASTRIDE];
    __shared__ __nv_bfloat16 Bsh[128*BSTRIDE];
    __shared__ __nv_bfloat16 Bsl[128*BSTRIDE];

    const int tid = threadIdx.x, wid = tid>>5, lane = tid&31;
    const int wm = wid>>2, wn = wid&3;          // warp grid 2 x 4
    const int bn = blockIdx.x, bm = blockIdx.y;
    const size_t arow0 = (size_t)bm*128;

    const u32 sAh = s2u(Ash), sAl = s2u(Asl), sBh = s2u(Bsh), sBl = s2u(Bsl);
    const u32* __restrict__ ph = (const u32*)Ahi;
    const u32* __restrict__ pl = (const u32*)Alo;

    float acc[4][4][4];
    #pragma unroll
    for (int i=0;i<4;i++)
        #pragma unroll
        for (int j=0;j<4;j++)
            #pragma unroll
            for (int q=0;q<4;q++) acc[i][j][q]=0.f;

    // ldmatrix source addresses (byte offsets into smem), fixed per thread
    const int a_r = (lane&7) + ((lane>>3)&1)*8;           // row within 16-row frag
    const int a_c = ((lane>>4)&1)*8;                      // col within 16 (bf16)
    const int b_n = ((lane>>4)&1)*8 + (lane&7);           // n within 16-row pair
    const int b_c = ((lane>>3)&1)*8;                      // k-col within 16

    for (int k0=0; k0<K; k0+=32){
        __syncthreads();
        // fill A hi/lo: 128 rows x 16 u32
        #pragma unroll
        for (int it=0; it<8; it++){
            int i = tid + it*256;
            int r = i>>4, cp = i&15;
            size_t gi = (arow0 + r)*(size_t)(K/2) + (k0>>1) + cp;
            Ash[r*ASTRIDE + cp] = ph[gi];
            Asl[r*ASTRIDE + cp] = pl[gi];
        }
        // fill B hi/lo: 128 n-rows x 32 k-cols  (B[n][k] = Bw[k0+k][bn*128+n])
        #pragma unroll
        for (int p=0; p<16; p++){
            int kk = p*2 + (tid>>7);
            int n  = tid&127;
            float v = Bw[(size_t)(k0+kk)*NTOT + bn*128 + n];
            __nv_bfloat16 hb = __float2bfloat16(v);
            Bsh[n*BSTRIDE + kk] = hb;
            Bsl[n*BSTRIDE + kk] = __float2bfloat16(v - __bfloat162float(hb));
        }
        __syncthreads();

        #pragma unroll
        for (int s=0; s<2; s++){
            u32 ah[4][4], al_[4][4], bh[2][4], bl_[2][4];
            #pragma unroll
            for (int fm=0; fm<4; fm++){
                u32 off = (u32)((wm*64 + fm*16 + a_r)*(ASTRIDE*4) + (s*16 + a_c)*2);
                ldsm4(ah[fm], sAh + off);
                ldsm4(al_[fm], sAl + off);
            }
            #pragma unroll
            for (int p=0; p<2; p++){
                u32 off = (u32)((wn*32 + p*16 + b_n)*(BSTRIDE*2) + (s*16 + b_c)*2);
                ldsm4(bh[p], sBh + off);
                ldsm4(bl_[p], sBl + off);
            }
            #pragma unroll
            for (int fm=0; fm<4; fm++){
                #pragma unroll
                for (int fn=0; fn<4; fn++){
                    const u32* bhf = &bh[fn>>1][(fn&1)*2];
                    const u32* blf = &bl_[fn>>1][(fn&1)*2];
                    mma16816(acc[fm][fn], ah[fm], bhf);   // hi*hi
                    mma16816(acc[fm][fn], ah[fm], blf);   // hi*lo
                    mma16816(acc[fm][fn], al_[fm], bhf);  // lo*hi
                }
            }
        }
    }

    // ---- writeback ----
    const int g = lane>>2, tg = lane&3;
    float* dst;
    int cbase, stride;
    if (MODE==0){
        if (bn < 6){ dst = g_xm; cbase = bn*128; }
        else       { dst = g_z;  cbase = bn*128 - DIN; }
        stride = DIN;
    } else {
        dst = outp; cbase = bn*128; stride = Dd;
    }
    #pragma unroll
    for (int fm=0; fm<4; fm++){
        #pragma unroll
        for (int fn=0; fn<4; fn++){
            int row = bm*128 + wm*64 + fm*16 + g;
            int col = cbase + wn*32 + fn*8 + tg*2;
            float* p0 = dst + (size_t)row*stride + col;
            p0[0] = acc[fm][fn][0]; p0[1] = acc[fm][fn][1];
            float* p1 = p0 + (size_t)8*stride;
            p1[0] = acc[fm][fn][2]; p1[1] = acc[fm][fn][3];
        }
    }
}

// ---------------- depthwise conv 3x3 + bias + silu (4 w-positions per thread) ----------------
__global__ void k_conv(const float* __restrict__ cw, const float* __restrict__ cb){
    const int d = blockIdx.x*256 + threadIdx.x;
    const int l0 = blockIdx.y*4;
    const int b = blockIdx.z;
    const int h = l0>>6, w0 = l0&63;

    float wt[9];
    #pragma unroll
    for (int i=0;i<9;i++) wt[i] = cw[d*9+i];
    const float bias = cb[d];
    float acc[4];
    #pragma unroll
    for (int q=0;q<4;q++) acc[q]=bias;

    const float* base = g_xm + (size_t)b*LL*DIN + d;
    #pragma unroll
    for (int di=-1; di<=1; di++){
        int hh = h+di;
        if (hh<0 || hh>=Hh) continue;
        const float* rowp = base + (size_t)hh*Ww*DIN;
        #pragma unroll
        for (int dj=-1; dj<=4; dj++){
            int col = w0+dj;
            if (col<0 || col>=Ww) continue;
            float v = rowp[(size_t)col*DIN];
            #pragma unroll
            for (int q=0;q<4;q++){
                int kx = dj - q + 1;
                if (kx>=0 && kx<=2) acc[q] = fmaf(v, wt[(di+1)*3 + kx], acc[q]);
            }
        }
    }
    #pragma unroll
    for (int q=0;q<4;q++){
        float v = fsilu(acc[q]);
        int l = l0+q;
        g_ue[((size_t)b*LL + l)*DIN + d] = v;
        int lt = (w0+q)*Hh + h;
        g_uo[((size_t)b*LL + lt)*DIN + d] = v;
    }
}

// ---------------- x_dbl GEMM (double-buffered, plain FFMA) ----------------
__global__ void sgemm_xdbl(){
    __shared__ float As[2][8][64];
    __shared__ float Bs[2][8][64];
    const int tid = threadIdx.x;
    const int z = blockIdx.z;
    const int b = z>>2, k = z&3;
    const float* A = ((k&1) ? g_uo : g_ue) + (size_t)b*LL*DIN;
    const float* Bp = g_xpwT + (size_t)k*DIN*C56;
    const int bj = blockIdx.x;

    float acc[4][4];
    #pragma unroll
    for (int i=0;i<4;i++)
        #pragma unroll
        for (int j=0;j<4;j++) acc[i][j]=0.f;

    const int arow = tid>>2, acol = (tid&3)*2;
    const int brw  = tid>>5, bcl  = (tid&31)*2;
    const int tm = tid>>4, tn = tid&15;

    float2 av = *(const float2*)(A + ((size_t)bj*64 + arow)*DIN + acol);
    float b0=0.f, b1=0.f;
    if (bcl < C56){ const float* bp = Bp + (size_t)brw*C56 + bcl; b0=bp[0]; b1=bp[1]; }
    As[0][acol][arow]=av.x; As[0][acol+1][arow]=av.y;
    Bs[0][brw][bcl]=b0; Bs[0][brw][bcl+1]=b1;
    __syncthreads();

    int buf = 0;
    for (int k0=8; k0<=DIN; k0+=8){
        const bool more = (k0 < DIN);
        if (more){
            av = *(const float2*)(A + ((size_t)bj*64 + arow)*DIN + k0 + acol);
            b0=0.f; b1=0.f;
            if (bcl < C56){ const float* bp = Bp + (size_t)(k0+brw)*C56 + bcl; b0=bp[0]; b1=bp[1]; }
        }
        #pragma unroll
        for (int kk=0;kk<8;kk++){
            float ar[4], br[4];
            *(float4*)ar = *(const float4*)&As[buf][kk][tm*4];
            *(float4*)br = *(const float4*)&Bs[buf][kk][tn*4];
            #pragma unroll
            for (int i=0;i<4;i++)
                #pragma unroll
                for (int j=0;j<4;j++) acc[i][j] = fmaf(ar[i], br[j], acc[i][j]);
        }
        if (more){
            const int nb = buf^1;
            As[nb][acol][arow]=av.x; As[nb][acol+1][arow]=av.y;
            Bs[nb][brw][bcl]=b0; Bs[nb][brw][bcl+1]=b1;
            __syncthreads();
            buf = nb;
        }
    }
    #pragma unroll
    for (int i=0;i<4;i++){
        int j = bj*64 + tm*4 + i;
        float* gp = g_G + ((size_t)z*LL + j)*C56 + tn*4;
        #pragma unroll
        for (int jj=0;jj<4;jj++){
            int c = tn*4 + jj;
            if (c < C56) gp[jj] = acc[i][jj];
        }
    }
}

// ---------------- Pass A: per-chunk local scan (h0=0) ----------------
__global__ void __launch_bounds__(256) k_scanA(const float* __restrict__ dtw_g,
                                               const float* __restrict__ dtb_g,
                                               const float* __restrict__ Ds_g){
    const int d = blockIdx.x*256 + threadIdx.x;
    const int c = blockIdx.y;
    const int z = blockIdx.z;            // b*4 + k
    const int b = z>>2, k = z&3;
    const int kd = k*DIN + d;

    float dtw[Rr];
    const float* wp = dtw_g + (size_t)kd*Rr;
    #pragma unroll
    for (int r=0;r<Rr;r++) dtw[r] = wp[r];
    const float bias = dtb_g[kd];
    float al[Nn];
    const float* ap = g_al + (size_t)kd*Nn;
    #pragma unroll
    for (int n=0;n<Nn;n++) al[n] = ap[n];
    const float al0 = al[0];
    bool pw = true;
    #pragma unroll
    for (int n=1;n<Nn;n++) pw = pw && (fabsf(al[n] - (float)(n+1)*al0) <= 1e-5f*fabsf(al[n]));
    const float Dv = Ds_g[kd];

    float h[Nn];
    #pragma unroll
    for (int n=0;n<Nn;n++) h[n]=0.f;
    float S = 0.f;

    const float* up = ((k&1) ? g_uo : g_ue) + (size_t)b*LL*DIN + d;
    const float* Gp = g_G + (size_t)z*LL*C56;
    float* cump = g_cum + (size_t)z*LL*DIN + d;
    float* yp = g_yp + ((size_t)(k*Bb + b))*LL*DIN + d;
    const bool rev = (k>=2);
    const int t0 = c*LC;

    if (pw){
        for (int tt=0; tt<LC; tt++){
            const int t = t0 + tt;
            const int j = rev ? (LL-1-t) : t;
            const float4* G4 = (const float4*)(Gp + (size_t)j*C56);
            const float u = up[(size_t)j*DIN];

            float accd = bias;
            #pragma unroll
            for (int q=0;q<6;q++){
                float4 g4 = G4[q];
                accd = fmaf(dtw[q*4+0], g4.x, accd);
                accd = fmaf(dtw[q*4+1], g4.y, accd);
                accd = fmaf(dtw[q*4+2], g4.z, accd);
                accd = fmaf(dtw[q*4+3], g4.w, accd);
            }
            const float delta = fsoftplus(accd);
            S += delta;
            cump[(size_t)j*DIN] = S;
            const float du = delta*u;

            float e[Nn];
            pow16(ex2f(delta*al0), e);

            float y = 0.f;
            #pragma unroll
            for (int g=0; g<4; g++){
                float4 Bv = G4[6+g];
                float4 Cv = G4[10+g];
                h[g*4+0]=fmaf(h[g*4+0],e[g*4+0],du*Bv.x); y=fmaf(h[g*4+0],Cv.x,y);
                h[g*4+1]=fmaf(h[g*4+1],e[g*4+1],du*Bv.y); y=fmaf(h[g*4+1],Cv.y,y);
                h[g*4+2]=fmaf(h[g*4+2],e[g*4+2],du*Bv.z); y=fmaf(h[g*4+2],Cv.z,y);
                h[g*4+3]=fmaf(h[g*4+3],e[g*4+3],du*Bv.w); y=fmaf(h[g*4+3],Cv.w,y);
            }
            yp[(size_t)j*DIN] = fmaf(Dv, u, y);
        }
    } else {
        for (int tt=0; tt<LC; tt++){
            const int t = t0 + tt;
            const int j = rev ? (LL-1-t) : t;
            const float4* G4 = (const float4*)(Gp + (size_t)j*C56);
            const float u = up[(size_t)j*DIN];

            float accd = bias;
            #pragma unroll
            for (int q=0;q<6;q++){
                float4 g4 = G4[q];
                accd = fmaf(dtw[q*4+0], g4.x, accd);
                accd = fmaf(dtw[q*4+1], g4.y, accd);
                accd = fmaf(dtw[q*4+2], g4.z, accd);
                accd = fmaf(dtw[q*4+3], g4.w, accd);
            }
            const float delta = fsoftplus(accd);
            S += delta;
            cump[(size_t)j*DIN] = S;
            const float du = delta*u;

            float y = 0.f;
            #pragma unroll
            for (int g=0; g<4; g++){
                float4 Bv = G4[6+g];
                float4 Cv = G4[10+g];
                float e;
                e = ex2f(delta*al[g*4+0]); h[g*4+0]=fmaf(h[g*4+0],e,du*Bv.x); y=fmaf(h[g*4+0],Cv.x,y);
                e = ex2f(delta*al[g*4+1]); h[g*4+1]=fmaf(h[g*4+1],e,du*Bv.y); y=fmaf(h[g*4+1],Cv.y,y);
                e = ex2f(delta*al[g*4+2]); h[g*4+2]=fmaf(h[g*4+2],e,du*Bv.z); y=fmaf(h[g*4+2],Cv.z,y);
                e = ex2f(delta*al[g*4+3]); h[g*4+3]=fmaf(h[g*4+3],e,du*Bv.w); y=fmaf(h[g*4+3],Cv.w,y);
            }
            yp[(size_t)j*DIN] = fmaf(Dv, u, y);
        }
    }
    float* hf = g_hf + (((size_t)z*NC + c)*DIN + d)*Nn;
    #pragma unroll
    for (int n=0;n<Nn;n++) hf[n] = h[n];
}

// ---------------- Pass B: sequential chunk-state combine ----------------
__global__ void __launch_bounds__(256) k_scanB(){
    const int d = blockIdx.x*256 + threadIdx.x;
    const int z = blockIdx.y;
    const int k = z&3;
    const int kd = k*DIN + d;
    const bool rev = (k>=2);

    float al[Nn];
    const float* ap = g_al + (size_t)kd*Nn;
    #pragma unroll
    for (int n=0;n<Nn;n++) al[n] = ap[n];

    float h0[Nn];
    #pragma unroll
    for (int n=0;n<Nn;n++) h0[n]=0.f;

    for (int c=0;c<NC;c++){
        float* hp = g_h0 + (((size_t)z*NC + c)*DIN + d)*Nn;
        #pragma unroll
        for (int n=0;n<Nn;n++) hp[n] = h0[n];
        const int t_last = c*LC + (LC-1);
        const int j_last = rev ? (LL-1-t_last) : t_last;
        const float S = g_cum[((size_t)z*LL + j_last)*DIN + d];
        const float* hf = g_hf + (((size_t)z*NC + c)*DIN + d)*Nn;
        #pragma unroll
        for (int n=0;n<Nn;n++){
            float e = ex2f(S*al[n]);
            h0[n] = fmaf(h0[n], e, hf[n]);
        }
    }
}

// ---------------- Pass C: apply cross-chunk correction to y ----------------
__global__ void __launch_bounds__(256) k_scanC(){
    const int c = blockIdx.y;
    if (c == 0) return;
    const int d = blockIdx.x*256 + threadIdx.x;
    const int z = blockIdx.z;
    const int b = z>>2, k = z&3;
    const int kd = k*DIN + d;
    const bool rev = (k>=2);

    float al[Nn], h0[Nn];
    const float* ap = g_al + (size_t)kd*Nn;
    const float* hp = g_h0 + (((size_t)z*NC + c)*DIN + d)*Nn;
    #pragma unroll
    for (int n=0;n<Nn;n++){ al[n] = ap[n]; h0[n] = hp[n]; }
    const float al0 = al[0];
    bool pw = true;
    #pragma unroll
    for (int n=1;n<Nn;n++) pw = pw && (fabsf(al[n] - (float)(n+1)*al0) <= 1e-5f*fabsf(al[n]));

    const float* Gp = g_G + (size_t)z*LL*C56 + Rr + Nn;   // C columns
    const float* cump = g_cum + (size_t)z*LL*DIN + d;
    float* yp = g_yp + ((size_t)(k*Bb + b))*LL*DIN + d;
    const int t0 = c*LC;

    if (pw){
        for (int tt=0; tt<LC; tt++){
            const int t = t0 + tt;
            const int j = rev ? (LL-1-t) : t;
            const float S = cump[(size_t)j*DIN];
            const float4* C4 = (const float4*)(Gp + (size_t)j*C56);
            float e[Nn];
            pow16(ex2f(S*al0), e);
            float corr = 0.f;
            #pragma unroll
            for (int g=0; g<4; g++){
                float4 Cv = C4[g];
                corr = fmaf(h0[g*4+0]*e[g*4+0], Cv.x, corr);
                corr = fmaf(h0[g*4+1]*e[g*4+1], Cv.y, corr);
                corr = fmaf(h0[g*4+2]*e[g*4+2], Cv.z, corr);
                corr = fmaf(h0[g*4+3]*e[g*4+3], Cv.w, corr);
            }
            yp[(size_t)j*DIN] += corr;
        }
    } else {
        for (int tt=0; tt<LC; tt++){
            const int t = t0 + tt;
            const int j = rev ? (LL-1-t) : t;
            const float S = cump[(size_t)j*DIN];
            const float4* C4 = (const float4*)(Gp + (size_t)j*C56);
            float corr = 0.f;
            #pragma unroll
            for (int g=0; g<4; g++){
                float4 Cv = C4[g];
                corr = fmaf(h0[g*4+0]*ex2f(S*al[g*4+0]), Cv.x, corr);
                corr = fmaf(h0[g*4+1]*ex2f(S*al[g*4+1]), Cv.y, corr);
                corr = fmaf(h0[g*4+2]*ex2f(S*al[g*4+2]), Cv.z, corr);
                corr = fmaf(h0[g*4+3]*ex2f(S*al[g*4+3]), Cv.w, corr);
            }
            yp[(size_t)j*DIN] += corr;
        }
    }
}

// ---------------- merge 4 directions + layernorm + gate (emit bf16 hi/lo act) ----------------
__device__ __forceinline__ float block_sum256(float v, float* sh){
    __syncthreads();
    #pragma unroll
    for (int o=16;o>0;o>>=1) v += __shfl_xor_sync(0xffffffffu, v, o);
    if ((threadIdx.x&31)==0) sh[threadIdx.x>>5] = v;
    __syncthreads();
    if (threadIdx.x < 32){
        float t = (threadIdx.x < 8) ? sh[threadIdx.x] : 0.f;
        #pragma unroll
        for (int o=4;o>0;o>>=1) t += __shfl_xor_sync(0xffffffffu, t, o);
        if (threadIdx.x==0) sh[0]=t;
    }
    __syncthreads();
    return sh[0];
}

__global__ void k_ln(const float* __restrict__ lng, const float* __restrict__ lnb){
    __shared__ float sh[32];
    const int bl = blockIdx.x;
    const int b = bl>>12, l = bl&4095;
    const int lt = (l&63)*Hh + (l>>6);

    float vals[3];
    float s = 0.f;
    #pragma unroll
    for (int i=0;i<3;i++){
        int d = threadIdx.x + i*256;
        size_t i0 = ((size_t)(0*Bb+b)*LL + l )*DIN + d;
        size_t i1 = ((size_t)(1*Bb+b)*LL + lt)*DIN + d;
        size_t i2 = ((size_t)(2*Bb+b)*LL + l )*DIN + d;
        size_t i3 = ((size_t)(3*Bb+b)*LL + lt)*DIN + d;
        float v = g_yp[i0] + g_yp[i2] + g_yp[i1] + g_yp[i3];
        vals[i] = v;
        s += v;
    }
    float tot = block_sum256(s, sh);
    const float mu = tot * (1.f/DIN);
    float s2 = 0.f;
    #pragma unroll
    for (int i=0;i<3;i++){ float cdev = vals[i]-mu; s2 += cdev*cdev; }
    float tot2 = block_sum256(s2, sh);
    const float rstd = rsqrtf(tot2*(1.f/DIN) + 1e-5f);

    #pragma unroll
    for (int i=0;i<3;i++){
        int d = threadIdx.x + i*256;
        float zn = g_z[(size_t)bl*DIN + d];
        float o = (vals[i]-mu)*rstd*lng[d] + lnb[d];
        float act = o * fsilu(zn);
        __nv_bfloat16 hb = __float2bfloat16(act);
        g_ahi[(size_t)bl*DIN + d] = hb;
        g_alo[(size_t)bl*DIN + d] = __float2bfloat16(act - __bfloat162float(hb));
    }
}

// ---------------- launch ----------------
extern "C" void kernel_launch(void* const* d_in, const int* in_sizes, int n_in,
                              void* d_out, int out_size){
    const float* x      = (const float*)d_in[0];
    const float* W_in   = (const float*)d_in[1];
    const float* conv_w = (const float*)d_in[2];
    const float* conv_b = (const float*)d_in[3];
    const float* xpw    = (const float*)d_in[4];
    const float* dtw    = (const float*)d_in[5];
    const float* dtb    = (const float*)d_in[6];
    const float* Alog   = (const float*)d_in[7];
    const float* Ds     = (const float*)d_in[8];
    const float* lng    = (const float*)d_in[9];
    const float* lnb    = (const float*)d_in[10];
    const float* W_out  = (const float*)d_in[11];
    float* out = (float*)d_out;

    k_xpwT<<<(Kk*DIN*C56 + 255)/256, 256>>>(xpw);
    k_altab<<<(Kk*DIN*Nn + 255)/256, 256>>>(Alog);
    k_cvt_x<<<(BL*Dd + 255)/256, 256>>>(x);
    hgemm<0><<<dim3(12, BL/128), 256>>>(W_in, nullptr);
    k_conv<<<dim3(DIN/256, LL/4, Bb), 256>>>(conv_w, conv_b);
    sgemm_xdbl<<<dim3(LL/64, 1, Bb*Kk), 256>>>();
    k_scanA<<<dim3(DIN/256, NC, Bb*Kk), 256>>>(dtw, dtb, Ds);
    k_scanB<<<dim3(DIN/256, Bb*Kk), 256>>>();
    k_scanC<<<dim3(DIN/256, NC, Bb*Kk), 256>>>();
    k_ln<<<BL, 256>>>(lng, lnb);
    hgemm<1><<<dim3(3, BL/128), 256>>>(W_out, out);
}

// round 13
// speedup vs baseline: 1.9246x; 1.0086x over previous
#include <cuda_runtime.h>
#include <cuda_bf16.h>

// ---------------- problem dims ----------------
#define Bb   8
#define Hh   64
#define Ww   64
#define Dd   384
#define DIN  768
#define Nn   16
#define Rr   24
#define Kk   4
#define LL   4096          // H*W
#define C56  56            // R + 2N
#define BL   (Bb*LL)       // 32768
#define LC   64            // chunk length for parallel scan
#define NC   (LL/LC)       // 64 chunks

typedef unsigned int       u32;
typedef unsigned long long u64;

// ---------------- scratch ----------------
__device__ float g_xm [Bb*LL*DIN];
__device__ float g_z  [Bb*LL*DIN];
__device__ float g_ue [Bb*LL*DIN];
__device__ float g_uo [Bb*LL*DIN];
__device__ float g_G  [(size_t)Bb*Kk*LL*C56];
__device__ float g_yp [(size_t)Kk*Bb*LL*DIN];
__device__ float g_xpwT[Kk*DIN*C56];
__device__ float g_cum[(size_t)Bb*Kk*LL*DIN];
__device__ float g_hf [(size_t)Bb*Kk*NC*DIN*Nn];
__device__ float g_h0 [(size_t)Bb*Kk*NC*DIN*Nn];
__device__ float g_al [Kk*DIN*Nn];                // A * log2(e)  (negative)
__device__ __nv_bfloat16 g_xhi[(size_t)BL*Dd];    // x split hi
__device__ __nv_bfloat16 g_xlo[(size_t)BL*Dd];    // x split lo
__device__ __nv_bfloat16 g_ahi[(size_t)BL*DIN];   // act split hi
__device__ __nv_bfloat16 g_alo[(size_t)BL*DIN];   // act split lo

// ---------------- fast math ----------------
__device__ __forceinline__ float ex2f(float x){ float r; asm("ex2.approx.f32 %0, %1;" : "=f"(r) : "f"(x)); return r; }
__device__ __forceinline__ float lg2f(float x){ float r; asm("lg2.approx.f32 %0, %1;" : "=f"(r) : "f"(x)); return r; }
#define LOG2E 1.4426950408889634f
#define LN2   0.6931471805599453f
__device__ __forceinline__ float fexp(float x){ return ex2f(x*LOG2E); }
__device__ __forceinline__ float fsilu(float x){ return x / (1.f + fexp(-x)); }
__device__ __forceinline__ float fsoftplus(float x){
    float e = fexp(-fabsf(x));
    return fmaxf(x, 0.f) + LN2 * lg2f(1.f + e);
}

// geometric powers: e[n] = w^(n+1)
__device__ __forceinline__ void pow16(float w, float* e){
    e[0]=w;  e[1]=w*w; e[2]=e[1]*w; e[3]=e[1]*e[1];
    e[4]=e[3]*e[0]; e[5]=e[3]*e[1]; e[6]=e[3]*e[2]; e[7]=e[3]*e[3];
    e[8]=e[7]*e[0]; e[9]=e[7]*e[1]; e[10]=e[7]*e[2]; e[11]=e[7]*e[3];
    e[12]=e[7]*e[4]; e[13]=e[7]*e[5]; e[14]=e[7]*e[6]; e[15]=e[7]*e[7];
}

// ---------------- warp-mma helpers (sm_80+ features, valid on plain sm_103) ----------------
__device__ __forceinline__ u32 s2u(const void* p){
    u32 a; asm("{ .reg .u64 t; cvta.to.shared.u64 t, %1; cvt.u32.u64 %0, t; }" : "=r"(a) : "l"(p)); return a;
}
__device__ __forceinline__ void ldsm4(u32* r, u32 addr){
    asm volatile("ldmatrix.sync.aligned.m8n8.x4.shared.b16 {%0,%1,%2,%3}, [%4];"
                 : "=r"(r[0]), "=r"(r[1]), "=r"(r[2]), "=r"(r[3]) : "r"(addr));
}
__device__ __forceinline__ void mma16816(float* c, const u32* a, const u32* b){
    asm volatile("mma.sync.aligned.m16n8k16.row.col.f32.bf16.bf16.f32 "
                 "{%0,%1,%2,%3}, {%4,%5,%6,%7}, {%8,%9}, {%0,%1,%2,%3};"
                 : "+f"(c[0]), "+f"(c[1]), "+f"(c[2]), "+f"(c[3])
                 : "r"(a[0]), "r"(a[1]), "r"(a[2]), "r"(a[3]), "r"(b[0]), "r"(b[1]));
}

// ---------------- prep ----------------
__global__ void k_xpwT(const float* __restrict__ xpw){
    int i = blockIdx.x*256 + threadIdx.x;
    if (i >= Kk*DIN*C56) return;
    int k = i / (DIN*C56);
    int rem = i - k*DIN*C56;
    int d = rem / C56;
    int c = rem - d*C56;
    g_xpwT[i] = xpw[(k*C56 + c)*DIN + d];
}
__global__ void k_altab(const float* __restrict__ Alog_g){
    int i = blockIdx.x*256 + threadIdx.x;
    if (i >= Kk*DIN*Nn) return;
    g_al[i] = -fexp(Alog_g[i]) * LOG2E;
}
__global__ void k_cvt_x(const float* __restrict__ in){
    int i = blockIdx.x*256 + threadIdx.x;
    if (i >= BL*Dd) return;
    float v = in[i];
    __nv_bfloat16 h = __float2bfloat16(v);
    g_xhi[i] = h;
    g_xlo[i] = __float2bfloat16(v - __bfloat162float(h));
}

// ---------------- bf16 3-product warp-MMA GEMM ----------------
// MODE 0: xin — A = g_xhi/g_xlo (BL x 384),  B = W_in (384x1536), out -> g_xm | g_z
// MODE 1: out — A = g_ahi/g_alo (BL x 768),  B = W_out (768x384), out -> outp
// Block: 128(M) x 128(N), 8 warps in 2x4, warp tile 64x32, K staged 32.
#define ASTRIDE 20   // u32 per A smem row (40 bf16, padded)
#define BSTRIDE 40   // bf16 per B smem row (padded)
template<int MODE>
__global__ void __launch_bounds__(256, 2) hgemm(const float* __restrict__ Bw, float* __restrict__ outp){
    constexpr int K    = (MODE==0) ? Dd : DIN;
    constexpr int NTOT = (MODE==0) ? 2*DIN : Dd;
    const __nv_bfloat16* Ahi = (MODE==0) ? g_xhi : g_ahi;
    const __nv_bfloat16* Alo = (MODE==0) ? g_xlo : g_alo;

    __shared__ u32 Ash[128*ASTRIDE];
    __shared__ u32 Asl[128*ASTRIDE];
    __shared__ __nv_bfloat16 Bsh[128*BSTRIDE];
    __shared__ __nv_bfloat16 Bsl[128*BSTRIDE];

    const int tid = threadIdx.x, wid = tid>>5, lane = tid&31;
    const int wm = wid>>2, wn = wid&3;          // warp grid 2 x 4
    const int bn = blockIdx.x, bm = blockIdx.y;
    const size_t arow0 = (size_t)bm*128;

    const u32 sAh = s2u(Ash), sAl = s2u(Asl), sBh = s2u(Bsh), sBl = s2u(Bsl);
    const u32* __restrict__ ph = (const u32*)Ahi;
    const u32* __restrict__ pl = (const u32*)Alo;

    float acc[4][4][4];
    #pragma unroll
    for (int i=0;i<4;i++)
        #pragma unroll
        for (int j=0;j<4;j++)
            #pragma unroll
            for (int q=0;q<4;q++) acc[i][j][q]=0.f;

    // ldmatrix source addresses (byte offsets into smem), fixed per thread
    const int a_r = (lane&7) + ((lane>>3)&1)*8;           // row within 16-row frag
    const int a_c = ((lane>>4)&1)*8;                      // col within 16 (bf16)
    const int b_n = ((lane>>4)&1)*8 + (lane&7);           // n within 16-row pair
    const int b_c = ((lane>>3)&1)*8;                      // k-col within 16

    for (int k0=0; k0<K; k0+=32){
        __syncthreads();
        // fill A hi/lo: 128 rows x 16 u32
        #pragma unroll
        for (int it=0; it<8; it++){
            int i = tid + it*256;
            int r = i>>4, cp = i&15;
            size_t gi = (arow0 + r)*(size_t)(K/2) + (k0>>1) + cp;
            Ash[r*ASTRIDE + cp] = ph[gi];
            Asl[r*ASTRIDE + cp] = pl[gi];
        }
        // fill B hi/lo: 128 n-rows x 32 k-cols  (B[n][k] = Bw[k0+k][bn*128+n])
        #pragma unroll
        for (int p=0; p<16; p++){
            int kk = p*2 + (tid>>7);
            int n  = tid&127;
            float v = Bw[(size_t)(k0+kk)*NTOT + bn*128 + n];
            __nv_bfloat16 hb = __float2bfloat16(v);
            Bsh[n*BSTRIDE + kk] = hb;
            Bsl[n*BSTRIDE + kk] = __float2bfloat16(v - __bfloat162float(hb));
        }
        __syncthreads();

        #pragma unroll
        for (int s=0; s<2; s++){
            u32 ah[4][4], al_[4][4], bh[2][4], bl_[2][4];
            #pragma unroll
            for (int fm=0; fm<4; fm++){
                u32 off = (u32)((wm*64 + fm*16 + a_r)*(ASTRIDE*4) + (s*16 + a_c)*2);
                ldsm4(ah[fm], sAh + off);
                ldsm4(al_[fm], sAl + off);
            }
            #pragma unroll
            for (int p=0; p<2; p++){
                u32 off = (u32)((wn*32 + p*16 + b_n)*(BSTRIDE*2) + (s*16 + b_c)*2);
                ldsm4(bh[p], sBh + off);
                ldsm4(bl_[p], sBl + off);
            }
            #pragma unroll
            for (int fm=0; fm<4; fm++){
                #pragma unroll
                for (int fn=0; fn<4; fn++){
                    const u32* bhf = &bh[fn>>1][(fn&1)*2];
                    const u32* blf = &bl_[fn>>1][(fn&1)*2];
                    mma16816(acc[fm][fn], ah[fm], bhf);   // hi*hi
                    mma16816(acc[fm][fn], ah[fm], blf);   // hi*lo
                    mma16816(acc[fm][fn], al_[fm], bhf);  // lo*hi
                }
            }
        }
    }

    // ---- writeback ----
    const int g = lane>>2, tg = lane&3;
    float* dst;
    int cbase, stride;
    if (MODE==0){
        if (bn < 6){ dst = g_xm; cbase = bn*128; }
        else       { dst = g_z;  cbase = bn*128 - DIN; }
        stride = DIN;
    } else {
        dst = outp; cbase = bn*128; stride = Dd;
    }
    #pragma unroll
    for (int fm=0; fm<4; fm++){
        #pragma unroll
        for (int fn=0; fn<4; fn++){
            int row = bm*128 + wm*64 + fm*16 + g;
            int col = cbase + wn*32 + fn*8 + tg*2;
            float* p0 = dst + (size_t)row*stride + col;
            p0[0] = acc[fm][fn][0]; p0[1] = acc[fm][fn][1];
            float* p1 = p0 + (size_t)8*stride;
            p1[0] = acc[fm][fn][2]; p1[1] = acc[fm][fn][3];
        }
    }
}

// ---------------- depthwise conv 3x3 + bias + silu (4 w-positions per thread) ----------------
__global__ void k_conv(const float* __restrict__ cw, const float* __restrict__ cb){
    const int d = blockIdx.x*256 + threadIdx.x;
    const int l0 = blockIdx.y*4;
    const int b = blockIdx.z;
    const int h = l0>>6, w0 = l0&63;

    float wt[9];
    #pragma unroll
    for (int i=0;i<9;i++) wt[i] = cw[d*9+i];
    const float bias = cb[d];
    float acc[4];
    #pragma unroll
    for (int q=0;q<4;q++) acc[q]=bias;

    const float* base = g_xm + (size_t)b*LL*DIN + d;
    #pragma unroll
    for (int di=-1; di<=1; di++){
        int hh = h+di;
        if (hh<0 || hh>=Hh) continue;
        const float* rowp = base + (size_t)hh*Ww*DIN;
        #pragma unroll
        for (int dj=-1; dj<=4; dj++){
            int col = w0+dj;
            if (col<0 || col>=Ww) continue;
            float v = rowp[(size_t)col*DIN];
            #pragma unroll
            for (int q=0;q<4;q++){
                int kx = dj - q + 1;
                if (kx>=0 && kx<=2) acc[q] = fmaf(v, wt[(di+1)*3 + kx], acc[q]);
            }
        }
    }
    #pragma unroll
    for (int q=0;q<4;q++){
        float v = fsilu(acc[q]);
        int l = l0+q;
        g_ue[((size_t)b*LL + l)*DIN + d] = v;
        int lt = (w0+q)*Hh + h;
        g_uo[((size_t)b*LL + lt)*DIN + d] = v;
    }
}

// ---------------- x_dbl GEMM (double-buffered, plain FFMA) ----------------
__global__ void sgemm_xdbl(){
    __shared__ float As[2][8][64];
    __shared__ float Bs[2][8][64];
    const int tid = threadIdx.x;
    const int z = blockIdx.z;
    const int b = z>>2, k = z&3;
    const float* A = ((k&1) ? g_uo : g_ue) + (size_t)b*LL*DIN;
    const float* Bp = g_xpwT + (size_t)k*DIN*C56;
    const int bj = blockIdx.x;

    float acc[4][4];
    #pragma unroll
    for (int i=0;i<4;i++)
        #pragma unroll
        for (int j=0;j<4;j++) acc[i][j]=0.f;

    const int arow = tid>>2, acol = (tid&3)*2;
    const int brw  = tid>>5, bcl  = (tid&31)*2;
    const int tm = tid>>4, tn = tid&15;

    float2 av = *(const float2*)(A + ((size_t)bj*64 + arow)*DIN + acol);
    float b0=0.f, b1=0.f;
    if (bcl < C56){ const float* bp = Bp + (size_t)brw*C56 + bcl; b0=bp[0]; b1=bp[1]; }
    As[0][acol][arow]=av.x; As[0][acol+1][arow]=av.y;
    Bs[0][brw][bcl]=b0; Bs[0][brw][bcl+1]=b1;
    __syncthreads();

    int buf = 0;
    for (int k0=8; k0<=DIN; k0+=8){
        const bool more = (k0 < DIN);
        if (more){
            av = *(const float2*)(A + ((size_t)bj*64 + arow)*DIN + k0 + acol);
            b0=0.f; b1=0.f;
            if (bcl < C56){ const float* bp = Bp + (size_t)(k0+brw)*C56 + bcl; b0=bp[0]; b1=bp[1]; }
        }
        #pragma unroll
        for (int kk=0;kk<8;kk++){
            float ar[4], br[4];
            *(float4*)ar = *(const float4*)&As[buf][kk][tm*4];
            *(float4*)br = *(const float4*)&Bs[buf][kk][tn*4];
            #pragma unroll
            for (int i=0;i<4;i++)
                #pragma unroll
                for (int j=0;j<4;j++) acc[i][j] = fmaf(ar[i], br[j], acc[i][j]);
        }
        if (more){
            const int nb = buf^1;
            As[nb][acol][arow]=av.x; As[nb][acol+1][arow]=av.y;
            Bs[nb][brw][bcl]=b0; Bs[nb][brw][bcl+1]=b1;
            __syncthreads();
            buf = nb;
        }
    }
    #pragma unroll
    for (int i=0;i<4;i++){
        int j = bj*64 + tm*4 + i;
        float* gp = g_G + ((size_t)z*LL + j)*C56 + tn*4;
        #pragma unroll
        for (int jj=0;jj<4;jj++){
            int c = tn*4 + jj;
            if (c < C56) gp[jj] = acc[i][jj];
        }
    }
}

// ---------------- Pass A: per-chunk local scan (h0=0) ----------------
__global__ void __launch_bounds__(256) k_scanA(const float* __restrict__ dtw_g,
                                               const float* __restrict__ dtb_g,
                                               const float* __restrict__ Ds_g){
    const int d = blockIdx.x*256 + threadIdx.x;
    const int c = blockIdx.y;
    const int z = blockIdx.z;            // b*4 + k
    const int b = z>>2, k = z&3;
    const int kd = k*DIN + d;

    float dtw[Rr];
    const float* wp = dtw_g + (size_t)kd*Rr;
    #pragma unroll
    for (int r=0;r<Rr;r++) dtw[r] = wp[r];
    const float bias = dtb_g[kd];
    float al[Nn];
    const float* ap = g_al + (size_t)kd*Nn;
    #pragma unroll
    for (int n=0;n<Nn;n++) al[n] = ap[n];
    const float al0 = al[0];
    bool pw = true;
    #pragma unroll
    for (int n=1;n<Nn;n++) pw = pw && (fabsf(al[n] - (float)(n+1)*al0) <= 1e-5f*fabsf(al[n]));
    const float Dv = Ds_g[kd];

    float h[Nn];
    #pragma unroll
    for (int n=0;n<Nn;n++) h[n]=0.f;
    float S = 0.f;

    const float* up = ((k&1) ? g_uo : g_ue) + (size_t)b*LL*DIN + d;
    const float* Gp = g_G + (size_t)z*LL*C56;
    float* cump = g_cum + (size_t)z*LL*DIN + d;
    float* yp = g_yp + ((size_t)(k*Bb + b))*LL*DIN + d;
    const bool rev = (k>=2);
    const int t0 = c*LC;

    if (pw){
        for (int tt=0; tt<LC; tt++){
            const int t = t0 + tt;
            const int j = rev ? (LL-1-t) : t;
            const float4* G4 = (const float4*)(Gp + (size_t)j*C56);
            const float u = up[(size_t)j*DIN];

            float accd = bias;
            #pragma unroll
            for (int q=0;q<6;q++){
                float4 g4 = G4[q];
                accd = fmaf(dtw[q*4+0], g4.x, accd);
                accd = fmaf(dtw[q*4+1], g4.y, accd);
                accd = fmaf(dtw[q*4+2], g4.z, accd);
                accd = fmaf(dtw[q*4+3], g4.w, accd);
            }
            const float delta = fsoftplus(accd);
            S += delta;
            cump[(size_t)j*DIN] = S;
            const float du = delta*u;

            float e[Nn];
            pow16(ex2f(delta*al0), e);

            float y = 0.f;
            #pragma unroll
            for (int g=0; g<4; g++){
                float4 Bv = G4[6+g];
                float4 Cv = G4[10+g];
                h[g*4+0]=fmaf(h[g*4+0],e[g*4+0],du*Bv.x); y=fmaf(h[g*4+0],Cv.x,y);
                h[g*4+1]=fmaf(h[g*4+1],e[g*4+1],du*Bv.y); y=fmaf(h[g*4+1],Cv.y,y);
                h[g*4+2]=fmaf(h[g*4+2],e[g*4+2],du*Bv.z); y=fmaf(h[g*4+2],Cv.z,y);
                h[g*4+3]=fmaf(h[g*4+3],e[g*4+3],du*Bv.w); y=fmaf(h[g*4+3],Cv.w,y);
            }
            yp[(size_t)j*DIN] = fmaf(Dv, u, y);
        }
    } else {
        for (int tt=0; tt<LC; tt++){
            const int t = t0 + tt;
            const int j = rev ? (LL-1-t) : t;
            const float4* G4 = (const float4*)(Gp + (size_t)j*C56);
            const float u = up[(size_t)j*DIN];

            float accd = bias;
            #pragma unroll
            for (int q=0;q<6;q++){
                float4 g4 = G4[q];
                accd = fmaf(dtw[q*4+0], g4.x, accd);
                accd = fmaf(dtw[q*4+1], g4.y, accd);
                accd = fmaf(dtw[q*4+2], g4.z, accd);
                accd = fmaf(dtw[q*4+3], g4.w, accd);
            }
            const float delta = fsoftplus(accd);
            S += delta;
            cump[(size_t)j*DIN] = S;
            const float du = delta*u;

            float y = 0.f;
            #pragma unroll
            for (int g=0; g<4; g++){
                float4 Bv = G4[6+g];
                float4 Cv = G4[10+g];
                float e;
                e = ex2f(delta*al[g*4+0]); h[g*4+0]=fmaf(h[g*4+0],e,du*Bv.x); y=fmaf(h[g*4+0],Cv.x,y);
                e = ex2f(delta*al[g*4+1]); h[g*4+1]=fmaf(h[g*4+1],e,du*Bv.y); y=fmaf(h[g*4+1],Cv.y,y);
                e = ex2f(delta*al[g*4+2]); h[g*4+2]=fmaf(h[g*4+2],e,du*Bv.z); y=fmaf(h[g*4+2],Cv.z,y);
                e = ex2f(delta*al[g*4+3]); h[g*4+3]=fmaf(h[g*4+3],e,du*Bv.w); y=fmaf(h[g*4+3],Cv.w,y);
            }
            yp[(size_t)j*DIN] = fmaf(Dv, u, y);
        }
    }
    float* hf = g_hf + (((size_t)z*NC + c)*DIN + d)*Nn;
    #pragma unroll
    for (int n=0;n<Nn;n++) hf[n] = h[n];
}

// ---------------- Pass B: sequential chunk-state combine ----------------
__global__ void __launch_bounds__(256) k_scanB(){
    const int d = blockIdx.x*256 + threadIdx.x;
    const int z = blockIdx.y;
    const int k = z&3;
    const int kd = k*DIN + d;
    const bool rev = (k>=2);

    float al[Nn];
    const float* ap = g_al + (size_t)kd*Nn;
    #pragma unroll
    for (int n=0;n<Nn;n++) al[n] = ap[n];

    float h0[Nn];
    #pragma unroll
    for (int n=0;n<Nn;n++) h0[n]=0.f;

    for (int c=0;c<NC;c++){
        float* hp = g_h0 + (((size_t)z*NC + c)*DIN + d)*Nn;
        #pragma unroll
        for (int n=0;n<Nn;n++) hp[n] = h0[n];
        const int t_last = c*LC + (LC-1);
        const int j_last = rev ? (LL-1-t_last) : t_last;
        const float S = g_cum[((size_t)z*LL + j_last)*DIN + d];
        const float* hf = g_hf + (((size_t)z*NC + c)*DIN + d)*Nn;
        #pragma unroll
        for (int n=0;n<Nn;n++){
            float e = ex2f(S*al[n]);
            h0[n] = fmaf(h0[n], e, hf[n]);
        }
    }
}

// ---------------- Pass C: apply cross-chunk correction to y ----------------
__global__ void __launch_bounds__(256) k_scanC(){
    const int c = blockIdx.y;
    if (c == 0) return;
    const int d = blockIdx.x*256 + threadIdx.x;
    const int z = blockIdx.z;
    const int b = z>>2, k = z&3;
    const int kd = k*DIN + d;
    const bool rev = (k>=2);

    float al[Nn], h0[Nn];
    const float* ap = g_al + (size_t)kd*Nn;
    const float* hp = g_h0 + (((size_t)z*NC + c)*DIN + d)*Nn;
    #pragma unroll
    for (int n=0;n<Nn;n++){ al[n] = ap[n]; h0[n] = hp[n]; }
    const float al0 = al[0];
    bool pw = true;
    #pragma unroll
    for (int n=1;n<Nn;n++) pw = pw && (fabsf(al[n] - (float)(n+1)*al0) <= 1e-5f*fabsf(al[n]));

    const float* Gp = g_G + (size_t)z*LL*C56 + Rr + Nn;   // C columns
    const float* cump = g_cum + (size_t)z*LL*DIN + d;
    float* yp = g_yp + ((size_t)(k*Bb + b))*LL*DIN + d;
    const int t0 = c*LC;

    if (pw){
        for (int tt=0; tt<LC; tt++){
            const int t = t0 + tt;
            const int j = rev ? (LL-1-t) : t;
            const float S = cump[(size_t)j*DIN];
            const float4* C4 = (const float4*)(Gp + (size_t)j*C56);
            float e[Nn];
            pow16(ex2f(S*al0), e);
            float corr = 0.f;
            #pragma unroll
            for (int g=0; g<4; g++){
                float4 Cv = C4[g];
                corr = fmaf(h0[g*4+0]*e[g*4+0], Cv.x, corr);
                corr = fmaf(h0[g*4+1]*e[g*4+1], Cv.y, corr);
                corr = fmaf(h0[g*4+2]*e[g*4+2], Cv.z, corr);
                corr = fmaf(h0[g*4+3]*e[g*4+3], Cv.w, corr);
            }
            yp[(size_t)j*DIN] += corr;
        }
    } else {
        for (int tt=0; tt<LC; tt++){
            const int t = t0 + tt;
            const int j = rev ? (LL-1-t) : t;
            const float S = cump[(size_t)j*DIN];
            const float4* C4 = (const float4*)(Gp + (size_t)j*C56);
            float corr = 0.f;
            #pragma unroll
            for (int g=0; g<4; g++){
                float4 Cv = C4[g];
                corr = fmaf(h0[g*4+0]*ex2f(S*al[g*4+0]), Cv.x, corr);
                corr = fmaf(h0[g*4+1]*ex2f(S*al[g*4+1]), Cv.y, corr);
                corr = fmaf(h0[g*4+2]*ex2f(S*al[g*4+2]), Cv.z, corr);
                corr = fmaf(h0[g*4+3]*ex2f(S*al[g*4+3]), Cv.w, corr);
            }
            yp[(size_t)j*DIN] += corr;
        }
    }
}

// ---------------- merge 4 directions + layernorm + gate (emit bf16 hi/lo act) ----------------
__device__ __forceinline__ float block_sum256(float v, float* sh){
    __syncthreads();
    #pragma unroll
    for (int o=16;o>0;o>>=1) v += __shfl_xor_sync(0xffffffffu, v, o);
    if ((threadIdx.x&31)==0) sh[threadIdx.x>>5] = v;
    __syncthreads();
    if (threadIdx.x < 32){
        float t = (threadIdx.x < 8) ? sh[threadIdx.x] : 0.f;
        #pragma unroll
        for (int o=4;o>0;o>>=1) t += __shfl_xor_sync(0xffffffffu, t, o);
        if (threadIdx.x==0) sh[0]=t;
    }
    __syncthreads();
    return sh[0];
}

__global__ void k_ln(const float* __restrict__ lng, const float* __restrict__ lnb){
    __shared__ float sh[32];
    const int bl = blockIdx.x;
    const int b = bl>>12, l = bl&4095;
    const int lt = (l&63)*Hh + (l>>6);

    float vals[3];
    float s = 0.f;
    #pragma unroll
    for (int i=0;i<3;i++){
        int d = threadIdx.x + i*256;
        size_t i0 = ((size_t)(0*Bb+b)*LL + l )*DIN + d;
        size_t i1 = ((size_t)(1*Bb+b)*LL + lt)*DIN + d;
        size_t i2 = ((size_t)(2*Bb+b)*LL + l )*DIN + d;
        size_t i3 = ((size_t)(3*Bb+b)*LL + lt)*DIN + d;
        float v = g_yp[i0] + g_yp[i2] + g_yp[i1] + g_yp[i3];
        vals[i] = v;
        s += v;
    }
    float tot = block_sum256(s, sh);
    const float mu = tot * (1.f/DIN);
    float s2 = 0.f;
    #pragma unroll
    for (int i=0;i<3;i++){ float cdev = vals[i]-mu; s2 += cdev*cdev; }
    float tot2 = block_sum256(s2, sh);
    const float rstd = rsqrtf(tot2*(1.f/DIN) + 1e-5f);

    #pragma unroll
    for (int i=0;i<3;i++){
        int d = threadIdx.x + i*256;
        float zn = g_z[(size_t)bl*DIN + d];
        float o = (vals[i]-mu)*rstd*lng[d] + lnb[d];
        float act = o * fsilu(zn);
        __nv_bfloat16 hb = __float2bfloat16(act);
        g_ahi[(size_t)bl*DIN + d] = hb;
        g_alo[(size_t)bl*DIN + d] = __float2bfloat16(act - __bfloat162float(hb));
    }
}

// ---------------- launch ----------------
extern "C" void kernel_launch(void* const* d_in, const int* in_sizes, int n_in,
                              void* d_out, int out_size){
    const float* x      = (const float*)d_in[0];
    const float* W_in   = (const float*)d_in[1];
    const float* conv_w = (const float*)d_in[2];
    const float* conv_b = (const float*)d_in[3];
    const float* xpw    = (const float*)d_in[4];
    const float* dtw    = (const float*)d_in[5];
    const float* dtb    = (const float*)d_in[6];
    const float* Alog   = (const float*)d_in[7];
    const float* Ds     = (const float*)d_in[8];
    const float* lng    = (const float*)d_in[9];
    const float* lnb    = (const float*)d_in[10];
    const float* W_out  = (const float*)d_in[11];
    float* out = (float*)d_out;

    k_xpwT<<<(Kk*DIN*C56 + 255)/256, 256>>>(xpw);
    k_altab<<<(Kk*DIN*Nn + 255)/256, 256>>>(Alog);
    k_cvt_x<<<(BL*Dd + 255)/256, 256>>>(x);
    hgemm<0><<<dim3(12, BL/128), 256>>>(W_in, nullptr);
    k_conv<<<dim3(DIN/256, LL/4, Bb), 256>>>(conv_w, conv_b);
    sgemm_xdbl<<<dim3(LL/64, 1, Bb*Kk), 256>>>();
    k_scanA<<<dim3(DIN/256, NC, Bb*Kk), 256>>>(dtw, dtb, Ds);
    k_scanB<<<dim3(DIN/256, Bb*Kk), 256>>>();
    k_scanC<<<dim3(DIN/256, NC, Bb*Kk), 256>>>();
    k_ln<<<BL, 256>>>(lng, lnb);
    hgemm<1><<<dim3(3, BL/128), 256>>>(W_out, out);
}

// round 14
// speedup vs baseline: 1.9307x; 1.0032x over previous
#include <cuda_runtime.h>
#include <cuda_bf16.h>

// ---------------- problem dims ----------------
#define Bb   8
#define Hh   64
#define Ww   64
#define Dd   384
#define DIN  768
#define Nn   16
#define Rr   24
#define Kk   4
#define LL   4096          // H*W
#define C56  56            // R + 2N
#define BL   (Bb*LL)       // 32768
#define LC   64            // chunk length for parallel scan
#define NC   (LL/LC)       // 64 chunks

typedef unsigned int       u32;
typedef unsigned long long u64;

// ---------------- scratch ----------------
__device__ float g_xm [Bb*LL*DIN];
__device__ float g_z  [Bb*LL*DIN];
__device__ float g_ue [Bb*LL*DIN];
__device__ float g_uo [Bb*LL*DIN];
__device__ float g_G  [(size_t)Bb*Kk*LL*C56];
__device__ float g_yp [(size_t)Kk*Bb*LL*DIN];
__device__ float g_xpwT[Kk*DIN*C56];
__device__ float g_cum[(size_t)Bb*Kk*LL*DIN];
__device__ float g_hf [(size_t)Bb*Kk*NC*DIN*Nn];
__device__ float g_h0 [(size_t)Bb*Kk*NC*DIN*Nn];
__device__ float g_al [Kk*DIN*Nn];                // A * log2(e)  (negative)
__device__ __nv_bfloat16 g_xhi[(size_t)BL*Dd];    // x split hi
__device__ __nv_bfloat16 g_xlo[(size_t)BL*Dd];    // x split lo
__device__ __nv_bfloat16 g_ahi[(size_t)BL*DIN];   // act split hi
__device__ __nv_bfloat16 g_alo[(size_t)BL*DIN];   // act split lo

// ---------------- fast math ----------------
__device__ __forceinline__ float ex2f(float x){ float r; asm("ex2.approx.f32 %0, %1;" : "=f"(r) : "f"(x)); return r; }
__device__ __forceinline__ float lg2f(float x){ float r; asm("lg2.approx.f32 %0, %1;" : "=f"(r) : "f"(x)); return r; }
#define LOG2E 1.4426950408889634f
#define LN2   0.6931471805599453f
__device__ __forceinline__ float fexp(float x){ return ex2f(x*LOG2E); }
__device__ __forceinline__ float fsilu(float x){ return x / (1.f + fexp(-x)); }
__device__ __forceinline__ float fsoftplus(float x){
    float e = fexp(-fabsf(x));
    return fmaxf(x, 0.f) + LN2 * lg2f(1.f + e);
}

// geometric powers: e[n] = w^(n+1)
__device__ __forceinline__ void pow16(float w, float* e){
    e[0]=w;  e[1]=w*w; e[2]=e[1]*w; e[3]=e[1]*e[1];
    e[4]=e[3]*e[0]; e[5]=e[3]*e[1]; e[6]=e[3]*e[2]; e[7]=e[3]*e[3];
    e[8]=e[7]*e[0]; e[9]=e[7]*e[1]; e[10]=e[7]*e[2]; e[11]=e[7]*e[3];
    e[12]=e[7]*e[4]; e[13]=e[7]*e[5]; e[14]=e[7]*e[6]; e[15]=e[7]*e[7];
}

// ---------------- warp-mma helpers (sm_80+ features, valid on plain sm_103) ----------------
__device__ __forceinline__ u32 s2u(const void* p){
    u32 a; asm("{ .reg .u64 t; cvta.to.shared.u64 t, %1; cvt.u32.u64 %0, t; }" : "=r"(a) : "l"(p)); return a;
}
__device__ __forceinline__ void ldsm4(u32* r, u32 addr){
    asm volatile("ldmatrix.sync.aligned.m8n8.x4.shared.b16 {%0,%1,%2,%3}, [%4];"
                 : "=r"(r[0]), "=r"(r[1]), "=r"(r[2]), "=r"(r[3]) : "r"(addr));
}
__device__ __forceinline__ void mma16816(float* c, const u32* a, const u32* b){
    asm volatile("mma.sync.aligned.m16n8k16.row.col.f32.bf16.bf16.f32 "
                 "{%0,%1,%2,%3}, {%4,%5,%6,%7}, {%8,%9}, {%0,%1,%2,%3};"
                 : "+f"(c[0]), "+f"(c[1]), "+f"(c[2]), "+f"(c[3])
                 : "r"(a[0]), "r"(a[1]), "r"(a[2]), "r"(a[3]), "r"(b[0]), "r"(b[1]));
}

// ---------------- prep ----------------
__global__ void k_xpwT(const float* __restrict__ xpw){
    int i = blockIdx.x*256 + threadIdx.x;
    if (i >= Kk*DIN*C56) return;
    int k = i / (DIN*C56);
    int rem = i - k*DIN*C56;
    int d = rem / C56;
    int c = rem - d*C56;
    g_xpwT[i] = xpw[(k*C56 + c)*DIN + d];
}
__global__ void k_altab(const float* __restrict__ Alog_g){
    int i = blockIdx.x*256 + threadIdx.x;
    if (i >= Kk*DIN*Nn) return;
    g_al[i] = -fexp(Alog_g[i]) * LOG2E;
}
__global__ void k_cvt_x(const float* __restrict__ in){
    int i = blockIdx.x*256 + threadIdx.x;
    if (i >= BL*Dd) return;
    float v = in[i];
    __nv_bfloat16 h = __float2bfloat16(v);
    g_xhi[i] = h;
    g_xlo[i] = __float2bfloat16(v - __bfloat162float(h));
}

// ---------------- bf16 3-product warp-MMA GEMM ----------------
// MODE 0: xin — A = g_xhi/g_xlo (BL x 384),  B = W_in (384x1536), out -> g_xm | g_z
// MODE 1: out — A = g_ahi/g_alo (BL x 768),  B = W_out (768x384), out -> outp
// Block: 128(M) x 128(N), 8 warps in 2x4, warp tile 64x32, K staged 32.
#define ASTRIDE 20   // u32 per A smem row (40 bf16, padded)
#define BSTRIDE 40   // bf16 per B smem row (padded)
template<int MODE>
__global__ void __launch_bounds__(256, 2) hgemm(const float* __restrict__ Bw, float* __restrict__ outp){
    constexpr int K    = (MODE==0) ? Dd : DIN;
    constexpr int NTOT = (MODE==0) ? 2*DIN : Dd;
    const __nv_bfloat16* Ahi = (MODE==0) ? g_xhi : g_ahi;
    const __nv_bfloat16* Alo = (MODE==0) ? g_xlo : g_alo;

    __shared__ u32 Ash[128*ASTRIDE];
    __shared__ u32 Asl[128*ASTRIDE];
    __shared__ __nv_bfloat16 Bsh[128*BSTRIDE];
    __shared__ __nv_bfloat16 Bsl[128*BSTRIDE];

    const int tid = threadIdx.x, wid = tid>>5, lane = tid&31;
    const int wm = wid>>2, wn = wid&3;          // warp grid 2 x 4
    const int bn = blockIdx.x, bm = blockIdx.y;
    const size_t arow0 = (size_t)bm*128;

    const u32 sAh = s2u(Ash), sAl = s2u(Asl), sBh = s2u(Bsh), sBl = s2u(Bsl);
    const u32* __restrict__ ph = (const u32*)Ahi;
    const u32* __restrict__ pl = (const u32*)Alo;

    float acc[4][4][4];
    #pragma unroll
    for (int i=0;i<4;i++)
        #pragma unroll
        for (int j=0;j<4;j++)
            #pragma unroll
            for (int q=0;q<4;q++) acc[i][j][q]=0.f;

    // ldmatrix source addresses (byte offsets into smem), fixed per thread
    const int a_r = (lane&7) + ((lane>>3)&1)*8;           // row within 16-row frag
    const int a_c = ((lane>>4)&1)*8;                      // col within 16 (bf16)
    const int b_n = ((lane>>4)&1)*8 + (lane&7);           // n within 16-row pair
    const int b_c = ((lane>>3)&1)*8;                      // k-col within 16

    for (int k0=0; k0<K; k0+=32){
        __syncthreads();
        // fill A hi/lo: 128 rows x 16 u32
        #pragma unroll
        for (int it=0; it<8; it++){
            int i = tid + it*256;
            int r = i>>4, cp = i&15;
            size_t gi = (arow0 + r)*(size_t)(K/2) + (k0>>1) + cp;
            Ash[r*ASTRIDE + cp] = ph[gi];
            Asl[r*ASTRIDE + cp] = pl[gi];
        }
        // fill B hi/lo: 128 n-rows x 32 k-cols  (B[n][k] = Bw[k0+k][bn*128+n])
        #pragma unroll
        for (int p=0; p<16; p++){
            int kk = p*2 + (tid>>7);
            int n  = tid&127;
            float v = Bw[(size_t)(k0+kk)*NTOT + bn*128 + n];
            __nv_bfloat16 hb = __float2bfloat16(v);
            Bsh[n*BSTRIDE + kk] = hb;
            Bsl[n*BSTRIDE + kk] = __float2bfloat16(v - __bfloat162float(hb));
        }
        __syncthreads();

        #pragma unroll
        for (int s=0; s<2; s++){
            u32 ah[4][4], al_[4][4], bh[2][4], bl_[2][4];
            #pragma unroll
            for (int fm=0; fm<4; fm++){
                u32 off = (u32)((wm*64 + fm*16 + a_r)*(ASTRIDE*4) + (s*16 + a_c)*2);
                ldsm4(ah[fm], sAh + off);
                ldsm4(al_[fm], sAl + off);
            }
            #pragma unroll
            for (int p=0; p<2; p++){
                u32 off = (u32)((wn*32 + p*16 + b_n)*(BSTRIDE*2) + (s*16 + b_c)*2);
                ldsm4(bh[p], sBh + off);
                ldsm4(bl_[p], sBl + off);
            }
            #pragma unroll
            for (int fm=0; fm<4; fm++){
                #pragma unroll
                for (int fn=0; fn<4; fn++){
                    const u32* bhf = &bh[fn>>1][(fn&1)*2];
                    const u32* blf = &bl_[fn>>1][(fn&1)*2];
                    mma16816(acc[fm][fn], ah[fm], bhf);   // hi*hi
                    mma16816(acc[fm][fn], ah[fm], blf);   // hi*lo
                    mma16816(acc[fm][fn], al_[fm], bhf);  // lo*hi
                }
            }
        }
    }

    // ---- writeback ----
    const int g = lane>>2, tg = lane&3;
    float* dst;
    int cbase, stride;
    if (MODE==0){
        if (bn < 6){ dst = g_xm; cbase = bn*128; }
        else       { dst = g_z;  cbase = bn*128 - DIN; }
        stride = DIN;
    } else {
        dst = outp; cbase = bn*128; stride = Dd;
    }
    #pragma unroll
    for (int fm=0; fm<4; fm++){
        #pragma unroll
        for (int fn=0; fn<4; fn++){
            int row = bm*128 + wm*64 + fm*16 + g;
            int col = cbase + wn*32 + fn*8 + tg*2;
            float* p0 = dst + (size_t)row*stride + col;
            p0[0] = acc[fm][fn][0]; p0[1] = acc[fm][fn][1];
            float* p1 = p0 + (size_t)8*stride;
            p1[0] = acc[fm][fn][2]; p1[1] = acc[fm][fn][3];
        }
    }
}

// ---------------- depthwise conv 3x3 + bias + silu (4 w-positions per thread) ----------------
__global__ void k_conv(const float* __restrict__ cw, const float* __restrict__ cb){
    const int d = blockIdx.x*256 + threadIdx.x;
    const int l0 = blockIdx.y*4;
    const int b = blockIdx.z;
    const int h = l0>>6, w0 = l0&63;

    float wt[9];
    #pragma unroll
    for (int i=0;i<9;i++) wt[i] = cw[d*9+i];
    const float bias = cb[d];
    float acc[4];
    #pragma unroll
    for (int q=0;q<4;q++) acc[q]=bias;

    const float* base = g_xm + (size_t)b*LL*DIN + d;
    #pragma unroll
    for (int di=-1; di<=1; di++){
        int hh = h+di;
        if (hh<0 || hh>=Hh) continue;
        const float* rowp = base + (size_t)hh*Ww*DIN;
        #pragma unroll
        for (int dj=-1; dj<=4; dj++){
            int col = w0+dj;
            if (col<0 || col>=Ww) continue;
            float v = rowp[(size_t)col*DIN];
            #pragma unroll
            for (int q=0;q<4;q++){
                int kx = dj - q + 1;
                if (kx>=0 && kx<=2) acc[q] = fmaf(v, wt[(di+1)*3 + kx], acc[q]);
            }
        }
    }
    #pragma unroll
    for (int q=0;q<4;q++){
        float v = fsilu(acc[q]);
        int l = l0+q;
        g_ue[((size_t)b*LL + l)*DIN + d] = v;
        int lt = (w0+q)*Hh + h;
        g_uo[((size_t)b*LL + lt)*DIN + d] = v;
    }
}

// ---------------- x_dbl GEMM (double-buffered, plain FFMA) ----------------
__global__ void sgemm_xdbl(){
    __shared__ float As[2][8][64];
    __shared__ float Bs[2][8][64];
    const int tid = threadIdx.x;
    const int z = blockIdx.z;
    const int b = z>>2, k = z&3;
    const float* A = ((k&1) ? g_uo : g_ue) + (size_t)b*LL*DIN;
    const float* Bp = g_xpwT + (size_t)k*DIN*C56;
    const int bj = blockIdx.x;

    float acc[4][4];
    #pragma unroll
    for (int i=0;i<4;i++)
        #pragma unroll
        for (int j=0;j<4;j++) acc[i][j]=0.f;

    const int arow = tid>>2, acol = (tid&3)*2;
    const int brw  = tid>>5, bcl  = (tid&31)*2;
    const int tm = tid>>4, tn = tid&15;

    float2 av = *(const float2*)(A + ((size_t)bj*64 + arow)*DIN + acol);
    float b0=0.f, b1=0.f;
    if (bcl < C56){ const float* bp = Bp + (size_t)brw*C56 + bcl; b0=bp[0]; b1=bp[1]; }
    As[0][acol][arow]=av.x; As[0][acol+1][arow]=av.y;
    Bs[0][brw][bcl]=b0; Bs[0][brw][bcl+1]=b1;
    __syncthreads();

    int buf = 0;
    for (int k0=8; k0<=DIN; k0+=8){
        const bool more = (k0 < DIN);
        if (more){
            av = *(const float2*)(A + ((size_t)bj*64 + arow)*DIN + k0 + acol);
            b0=0.f; b1=0.f;
            if (bcl < C56){ const float* bp = Bp + (size_t)(k0+brw)*C56 + bcl; b0=bp[0]; b1=bp[1]; }
        }
        #pragma unroll
        for (int kk=0;kk<8;kk++){
            float ar[4], br[4];
            *(float4*)ar = *(const float4*)&As[buf][kk][tm*4];
            *(float4*)br = *(const float4*)&Bs[buf][kk][tn*4];
            #pragma unroll
            for (int i=0;i<4;i++)
                #pragma unroll
                for (int j=0;j<4;j++) acc[i][j] = fmaf(ar[i], br[j], acc[i][j]);
        }
        if (more){
            const int nb = buf^1;
            As[nb][acol][arow]=av.x; As[nb][acol+1][arow]=av.y;
            Bs[nb][brw][bcl]=b0; Bs[nb][brw][bcl+1]=b1;
            __syncthreads();
            buf = nb;
        }
    }
    #pragma unroll
    for (int i=0;i<4;i++){
        int j = bj*64 + tm*4 + i;
        float* gp = g_G + ((size_t)z*LL + j)*C56 + tn*4;
        #pragma unroll
        for (int jj=0;jj<4;jj++){
            int c = tn*4 + jj;
            if (c < C56) gp[jj] = acc[i][jj];
        }
    }
}

// ---------------- Pass A: per-chunk local scan (h0=0) ----------------
__global__ void __launch_bounds__(256) k_scanA(const float* __restrict__ dtw_g,
                                               const float* __restrict__ dtb_g,
                                               const float* __restrict__ Ds_g){
    const int d = blockIdx.x*256 + threadIdx.x;
    const int c = blockIdx.y;
    const int z = blockIdx.z;            // b*4 + k
    const int b = z>>2, k = z&3;
    const int kd = k*DIN + d;

    float dtw[Rr];
    const float* wp = dtw_g + (size_t)kd*Rr;
    #pragma unroll
    for (int r=0;r<Rr;r++) dtw[r] = wp[r];
    const float bias = dtb_g[kd];
    float al[Nn];
    const float* ap = g_al + (size_t)kd*Nn;
    #pragma unroll
    for (int n=0;n<Nn;n++) al[n] = ap[n];
    const float al0 = al[0];
    bool pw = true;
    #pragma unroll
    for (int n=1;n<Nn;n++) pw = pw && (fabsf(al[n] - (float)(n+1)*al0) <= 1e-5f*fabsf(al[n]));
    const float Dv = Ds_g[kd];

    float h[Nn];
    #pragma unroll
    for (int n=0;n<Nn;n++) h[n]=0.f;
    float S = 0.f;

    const float* up = ((k&1) ? g_uo : g_ue) + (size_t)b*LL*DIN + d;
    const float* Gp = g_G + (size_t)z*LL*C56;
    float* cump = g_cum + (size_t)z*LL*DIN + d;
    float* yp = g_yp + ((size_t)(k*Bb + b))*LL*DIN + d;
    const bool rev = (k>=2);
    const int t0 = c*LC;

    if (pw){
        for (int tt=0; tt<LC; tt++){
            const int t = t0 + tt;
            const int j = rev ? (LL-1-t) : t;
            const float4* G4 = (const float4*)(Gp + (size_t)j*C56);
            const float u = up[(size_t)j*DIN];

            float accd = bias;
            #pragma unroll
            for (int q=0;q<6;q++){
                float4 g4 = G4[q];
                accd = fmaf(dtw[q*4+0], g4.x, accd);
                accd = fmaf(dtw[q*4+1], g4.y, accd);
                accd = fmaf(dtw[q*4+2], g4.z, accd);
                accd = fmaf(dtw[q*4+3], g4.w, accd);
            }
            const float delta = fsoftplus(accd);
            S += delta;
            cump[(size_t)j*DIN] = S;
            const float du = delta*u;

            float e[Nn];
            pow16(ex2f(delta*al0), e);

            float y = 0.f;
            #pragma unroll
            for (int g=0; g<4; g++){
                float4 Bv = G4[6+g];
                float4 Cv = G4[10+g];
                h[g*4+0]=fmaf(h[g*4+0],e[g*4+0],du*Bv.x); y=fmaf(h[g*4+0],Cv.x,y);
                h[g*4+1]=fmaf(h[g*4+1],e[g*4+1],du*Bv.y); y=fmaf(h[g*4+1],Cv.y,y);
                h[g*4+2]=fmaf(h[g*4+2],e[g*4+2],du*Bv.z); y=fmaf(h[g*4+2],Cv.z,y);
                h[g*4+3]=fmaf(h[g*4+3],e[g*4+3],du*Bv.w); y=fmaf(h[g*4+3],Cv.w,y);
            }
            yp[(size_t)j*DIN] = fmaf(Dv, u, y);
        }
    } else {
        for (int tt=0; tt<LC; tt++){
            const int t = t0 + tt;
            const int j = rev ? (LL-1-t) : t;
            const float4* G4 = (const float4*)(Gp + (size_t)j*C56);
            const float u = up[(size_t)j*DIN];

            float accd = bias;
            #pragma unroll
            for (int q=0;q<6;q++){
                float4 g4 = G4[q];
                accd = fmaf(dtw[q*4+0], g4.x, accd);
                accd = fmaf(dtw[q*4+1], g4.y, accd);
                accd = fmaf(dtw[q*4+2], g4.z, accd);
                accd = fmaf(dtw[q*4+3], g4.w, accd);
            }
            const float delta = fsoftplus(accd);
            S += delta;
            cump[(size_t)j*DIN] = S;
            const float du = delta*u;

            float y = 0.f;
            #pragma unroll
            for (int g=0; g<4; g++){
                float4 Bv = G4[6+g];
                float4 Cv = G4[10+g];
                float e;
                e = ex2f(delta*al[g*4+0]); h[g*4+0]=fmaf(h[g*4+0],e,du*Bv.x); y=fmaf(h[g*4+0],Cv.x,y);
                e = ex2f(delta*al[g*4+1]); h[g*4+1]=fmaf(h[g*4+1],e,du*Bv.y); y=fmaf(h[g*4+1],Cv.y,y);
                e = ex2f(delta*al[g*4+2]); h[g*4+2]=fmaf(h[g*4+2],e,du*Bv.z); y=fmaf(h[g*4+2],Cv.z,y);
                e = ex2f(delta*al[g*4+3]); h[g*4+3]=fmaf(h[g*4+3],e,du*Bv.w); y=fmaf(h[g*4+3],Cv.w,y);
            }
            yp[(size_t)j*DIN] = fmaf(Dv, u, y);
        }
    }
    float* hf = g_hf + (((size_t)z*NC + c)*DIN + d)*Nn;
    #pragma unroll
    for (int n=0;n<Nn;n++) hf[n] = h[n];
}

// ---------------- Pass B: sequential chunk-state combine ----------------
__global__ void __launch_bounds__(256) k_scanB(){
    const int d = blockIdx.x*256 + threadIdx.x;
    const int z = blockIdx.y;
    const int k = z&3;
    const int kd = k*DIN + d;
    const bool rev = (k>=2);

    float al[Nn];
    const float* ap = g_al + (size_t)kd*Nn;
    #pragma unroll
    for (int n=0;n<Nn;n++) al[n] = ap[n];

    float h0[Nn];
    #pragma unroll
    for (int n=0;n<Nn;n++) h0[n]=0.f;

    for (int c=0;c<NC;c++){
        float* hp = g_h0 + (((size_t)z*NC + c)*DIN + d)*Nn;
        #pragma unroll
        for (int n=0;n<Nn;n++) hp[n] = h0[n];
        const int t_last = c*LC + (LC-1);
        const int j_last = rev ? (LL-1-t_last) : t_last;
        const float S = g_cum[((size_t)z*LL + j_last)*DIN + d];
        const float* hf = g_hf + (((size_t)z*NC + c)*DIN + d)*Nn;
        #pragma unroll
        for (int n=0;n<Nn;n++){
            float e = ex2f(S*al[n]);
            h0[n] = fmaf(h0[n], e, hf[n]);
        }
    }
}

// ---------------- Pass C: apply cross-chunk correction to y ----------------
__global__ void __launch_bounds__(256) k_scanC(){
    const int c = blockIdx.y;
    if (c == 0) return;
    const int d = blockIdx.x*256 + threadIdx.x;
    const int z = blockIdx.z;
    const int b = z>>2, k = z&3;
    const int kd = k*DIN + d;
    const bool rev = (k>=2);

    float al[Nn], h0[Nn];
    const float* ap = g_al + (size_t)kd*Nn;
    const float* hp = g_h0 + (((size_t)z*NC + c)*DIN + d)*Nn;
    #pragma unroll
    for (int n=0;n<Nn;n++){ al[n] = ap[n]; h0[n] = hp[n]; }
    const float al0 = al[0];
    bool pw = true;
    #pragma unroll
    for (int n=1;n<Nn;n++) pw = pw && (fabsf(al[n] - (float)(n+1)*al0) <= 1e-5f*fabsf(al[n]));

    const float* Gp = g_G + (size_t)z*LL*C56 + Rr + Nn;   // C columns
    const float* cump = g_cum + (size_t)z*LL*DIN + d;
    float* yp = g_yp + ((size_t)(k*Bb + b))*LL*DIN + d;
    const int t0 = c*LC;

    if (pw){
        for (int tt=0; tt<LC; tt++){
            const int t = t0 + tt;
            const int j = rev ? (LL-1-t) : t;
            const float S = cump[(size_t)j*DIN];
            const float4* C4 = (const float4*)(Gp + (size_t)j*C56);
            float e[Nn];
            pow16(ex2f(S*al0), e);
            float corr = 0.f;
            #pragma unroll
            for (int g=0; g<4; g++){
                float4 Cv = C4[g];
                corr = fmaf(h0[g*4+0]*e[g*4+0], Cv.x, corr);
                corr = fmaf(h0[g*4+1]*e[g*4+1], Cv.y, corr);
                corr = fmaf(h0[g*4+2]*e[g*4+2], Cv.z, corr);
                corr = fmaf(h0[g*4+3]*e[g*4+3], Cv.w, corr);
            }
            yp[(size_t)j*DIN] += corr;
        }
    } else {
        for (int tt=0; tt<LC; tt++){
            const int t = t0 + tt;
            const int j = rev ? (LL-1-t) : t;
            const float S = cump[(size_t)j*DIN];
            const float4* C4 = (const float4*)(Gp + (size_t)j*C56);
            float corr = 0.f;
            #pragma unroll
            for (int g=0; g<4; g++){
                float4 Cv = C4[g];
                corr = fmaf(h0[g*4+0]*ex2f(S*al[g*4+0]), Cv.x, corr);
                corr = fmaf(h0[g*4+1]*ex2f(S*al[g*4+1]), Cv.y, corr);
                corr = fmaf(h0[g*4+2]*ex2f(S*al[g*4+2]), Cv.z, corr);
                corr = fmaf(h0[g*4+3]*ex2f(S*al[g*4+3]), Cv.w, corr);
            }
            yp[(size_t)j*DIN] += corr;
        }
    }
}

// ---------------- merge 4 directions + layernorm + gate (emit bf16 hi/lo act) ----------------
__device__ __forceinline__ float block_sum256(float v, float* sh){
    __syncthreads();
    #pragma unroll
    for (int o=16;o>0;o>>=1) v += __shfl_xor_sync(0xffffffffu, v, o);
    if ((threadIdx.x&31)==0) sh[threadIdx.x>>5] = v;
    __syncthreads();
    if (threadIdx.x < 32){
        float t = (threadIdx.x < 8) ? sh[threadIdx.x] : 0.f;
        #pragma unroll
        for (int o=4;o>0;o>>=1) t += __shfl_xor_sync(0xffffffffu, t, o);
        if (threadIdx.x==0) sh[0]=t;
    }
    __syncthreads();
    return sh[0];
}

__global__ void k_ln(const float* __restrict__ lng, const float* __restrict__ lnb){
    __shared__ float sh[32];
    const int bl = blockIdx.x;
    const int b = bl>>12, l = bl&4095;
    const int lt = (l&63)*Hh + (l>>6);

    float vals[3];
    float s = 0.f;
    #pragma unroll
    for (int i=0;i<3;i++){
        int d = threadIdx.x + i*256;
        size_t i0 = ((size_t)(0*Bb+b)*LL + l )*DIN + d;
        size_t i1 = ((size_t)(1*Bb+b)*LL + lt)*DIN + d;
        size_t i2 = ((size_t)(2*Bb+b)*LL + l )*DIN + d;
        size_t i3 = ((size_t)(3*Bb+b)*LL + lt)*DIN + d;
        float v = g_yp[i0] + g_yp[i2] + g_yp[i1] + g_yp[i3];
        vals[i] = v;
        s += v;
    }
    float tot = block_sum256(s, sh);
    const float mu = tot * (1.f/DIN);
    float s2 = 0.f;
    #pragma unroll
    for (int i=0;i<3;i++){ float cdev = vals[i]-mu; s2 += cdev*cdev; }
    float tot2 = block_sum256(s2, sh);
    const float rstd = rsqrtf(tot2*(1.f/DIN) + 1e-5f);

    #pragma unroll
    for (int i=0;i<3;i++){
        int d = threadIdx.x + i*256;
        float zn = g_z[(size_t)bl*DIN + d];
        float o = (vals[i]-mu)*rstd*lng[d] + lnb[d];
        float act = o * fsilu(zn);
        __nv_bfloat16 hb = __float2bfloat16(act);
        g_ahi[(size_t)bl*DIN + d] = hb;
        g_alo[(size_t)bl*DIN + d] = __float2bfloat16(act - __bfloat162float(hb));
    }
}

// ---------------- launch ----------------
extern "C" void kernel_launch(void* const* d_in, const int* in_sizes, int n_in,
                              void* d_out, int out_size){
    const float* x      = (const float*)d_in[0];
    const float* W_in   = (const float*)d_in[1];
    const float* conv_w = (const float*)d_in[2];
    const float* conv_b = (const float*)d_in[3];
    const float* xpw    = (const float*)d_in[4];
    const float* dtw    = (const float*)d_in[5];
    const float* dtb    = (const float*)d_in[6];
    const float* Alog   = (const float*)d_in[7];
    const float* Ds     = (const float*)d_in[8];
    const float* lng    = (const float*)d_in[9];
    const float* lnb    = (const float*)d_in[10];
    const float* W_out  = (const float*)d_in[11];
    float* out = (float*)d_out;

    k_xpwT<<<(Kk*DIN*C56 + 255)/256, 256>>>(xpw);
    k_altab<<<(Kk*DIN*Nn + 255)/256, 256>>>(Alog);
    k_cvt_x<<<(BL*Dd + 255)/256, 256>>>(x);
    hgemm<0><<<dim3(12, BL/128), 256>>>(W_in, nullptr);
    k_conv<<<dim3(DIN/256, LL/4, Bb), 256>>>(conv_w, conv_b);
    sgemm_xdbl<<<dim3(LL/64, 1, Bb*Kk), 256>>>();
    k_scanA<<<dim3(DIN/256, NC, Bb*Kk), 256>>>(dtw, dtb, Ds);
    k_scanB<<<dim3(DIN/256, Bb*Kk), 256>>>();
    k_scanC<<<dim3(DIN/256, NC, Bb*Kk), 256>>>();
    k_ln<<<BL, 256>>>(lng, lnb);
    hgemm<1><<<dim3(3, BL/128), 256>>>(W_out, out);
}